// round 3
// baseline (speedup 1.0000x reference)
#include <cuda_runtime.h>
#include <cuda_bf16.h>
#include <cstddef>

// Problem constants
#define BATCH 2
#define SEQ   2048
#define DMODEL 1024
#define NHEADS 16
#define HD    64
#define ROWS  (BATCH*SEQ)          // 4096
#define QKV_N (3*DMODEL)           // 3072

// Scratch (allocation-free rule: __device__ globals)
__device__ float g_qkv[(size_t)ROWS * QKV_N];   // [row, 3*D] row = b*SEQ+s
__device__ float g_ctx[(size_t)ROWS * DMODEL];  // [row, D]   (b,s,h,d) packed

// ---------------------------------------------------------------------------
// SGEMM: C[M,N] = A[M,K] @ B[K,N] + bias[N]
// BM=BN=64, BK=16, 256 threads, 4x4 per thread
// ---------------------------------------------------------------------------
__global__ __launch_bounds__(256) void sgemm_bias_kernel(
    int M, int N, int K,
    const float* __restrict__ A,
    const float* __restrict__ B,
    const float* __restrict__ bias,
    float* __restrict__ C)
{
    const int BM = 64, BN = 64, BK = 16;
    __shared__ float As[BK][BM];   // transposed A tile
    __shared__ float Bs[BK][BN];

    int tid = threadIdx.x;
    int bm = blockIdx.y * BM;
    int bn = blockIdx.x * BN;

    int tx = tid & 15;        // 0..15 -> N direction (x4)
    int ty = tid >> 4;        // 0..15 -> M direction (x4)

    // A tile load: 64x16 floats, each thread one float4 along K
    int arow = tid >> 2;            // 0..63
    int ak   = (tid & 3) * 4;       // 0,4,8,12
    // B tile load: 16x64 floats, each thread one float4 along N
    int brow = tid >> 4;            // 0..15
    int bc   = (tid & 15) * 4;      // 0..60

    const float* Aptr = A + (size_t)(bm + arow) * K + ak;
    const float* Bptr = B + (size_t)brow * N + bn + bc;

    float acc[4][4];
    #pragma unroll
    for (int i = 0; i < 4; i++)
        #pragma unroll
        for (int j = 0; j < 4; j++) acc[i][j] = 0.f;

    for (int k0 = 0; k0 < K; k0 += BK) {
        float4 a4 = *(const float4*)(Aptr + k0);
        As[ak + 0][arow] = a4.x;
        As[ak + 1][arow] = a4.y;
        As[ak + 2][arow] = a4.z;
        As[ak + 3][arow] = a4.w;
        float4 b4 = *(const float4*)(Bptr + (size_t)k0 * N);
        *(float4*)&Bs[brow][bc] = b4;
        __syncthreads();

        #pragma unroll
        for (int k = 0; k < BK; k++) {
            float af[4], bf[4];
            *(float4*)af = *(const float4*)&As[k][ty * 4];
            *(float4*)bf = *(const float4*)&Bs[k][tx * 4];
            #pragma unroll
            for (int i = 0; i < 4; i++)
                #pragma unroll
                for (int j = 0; j < 4; j++)
                    acc[i][j] += af[i] * bf[j];
        }
        __syncthreads();
    }

    float4 bv = *(const float4*)(bias + bn + tx * 4);
    #pragma unroll
    for (int i = 0; i < 4; i++) {
        int row = bm + ty * 4 + i;
        float4 o;
        o.x = acc[i][0] + bv.x;
        o.y = acc[i][1] + bv.y;
        o.z = acc[i][2] + bv.z;
        o.w = acc[i][3] + bv.w;
        *(float4*)(C + (size_t)row * N + bn + tx * 4) = o;
    }
}

// ---------------------------------------------------------------------------
// Causal flash attention (fp32). One block = 64 q rows of one (b,h).
// 64 threads, each owns one q row; q + acc register-resident.
// ---------------------------------------------------------------------------
__global__ __launch_bounds__(64) void attn_kernel(
    const float* __restrict__ qkv, float* __restrict__ ctx)
{
    int qi = blockIdx.x;              // q tile 0..31
    int bh = blockIdx.y;              // b*NHEADS + h
    int b  = bh >> 4;
    int h  = bh & 15;
    int t  = threadIdx.x;             // 0..63 = row within tile

    __shared__ float Ks[64][HD];
    __shared__ float Vs[64][HD];
    __shared__ float Ss[64][65];      // padded: conflict-free column writes

    const float scale = 0.125f;       // 1/sqrt(64)
    int qrow = qi * 64 + t;

    const float* qptr = qkv + (size_t)(b * SEQ + qrow) * QKV_N + h * HD;
    float q[HD];
    #pragma unroll
    for (int i = 0; i < 16; i++) {
        float4 v = *(const float4*)(qptr + i * 4);
        q[i*4+0] = v.x; q[i*4+1] = v.y; q[i*4+2] = v.z; q[i*4+3] = v.w;
    }

    float acc[HD];
    #pragma unroll
    for (int i = 0; i < HD; i++) acc[i] = 0.f;
    float m = -3.0e38f, l = 0.f;

    for (int kt = 0; kt <= qi; ++kt) {
        __syncthreads();   // previous iteration's Vs reads done
        // Load K,V tiles (coalesced: consecutive threads -> consecutive dims)
        const float* kbase = qkv + (size_t)(b * SEQ + kt * 64) * QKV_N + DMODEL + h * HD;
        #pragma unroll
        for (int i = 0; i < 16; i++) {
            int idx = i * 64 + t;
            int row = idx >> 4;
            int c4  = (idx & 15) * 4;
            const float* kp = kbase + (size_t)row * QKV_N + c4;
            *(float4*)&Ks[row][c4] = *(const float4*)kp;
            *(float4*)&Vs[row][c4] = *(const float4*)(kp + DMODEL);
        }
        __syncthreads();

        bool diag = (kt == qi);
        float mt = m;
        // Phase 1: scores for this tile
        for (int j = 0; j < 64; ++j) {
            float s0 = 0.f, s1 = 0.f, s2 = 0.f, s3 = 0.f;
            #pragma unroll
            for (int i = 0; i < 16; i++) {
                float4 k4 = *(const float4*)&Ks[j][i * 4];
                s0 += q[i*4+0] * k4.x;
                s1 += q[i*4+1] * k4.y;
                s2 += q[i*4+2] * k4.z;
                s3 += q[i*4+3] * k4.w;
            }
            float s = ((s0 + s1) + (s2 + s3)) * scale;
            if (diag && j > t) s = -3.0e38f;
            Ss[t][j] = s;
            mt = fmaxf(mt, s);
        }
        // Rescale
        float corr = __expf(m - mt);
        m = mt;
        l *= corr;
        #pragma unroll
        for (int i = 0; i < HD; i++) acc[i] *= corr;
        // Phase 2: probs @ V
        for (int j = 0; j < 64; ++j) {
            float p = __expf(Ss[t][j] - m);
            l += p;
            #pragma unroll
            for (int i = 0; i < 16; i++) {
                float4 v4 = *(const float4*)&Vs[j][i * 4];
                acc[i*4+0] += p * v4.x;
                acc[i*4+1] += p * v4.y;
                acc[i*4+2] += p * v4.z;
                acc[i*4+3] += p * v4.w;
            }
        }
    }

    float inv = 1.f / l;
    float* optr = ctx + (size_t)(b * SEQ + qrow) * DMODEL + h * HD;
    #pragma unroll
    for (int i = 0; i < 16; i++) {
        float4 o;
        o.x = acc[i*4+0] * inv;
        o.y = acc[i*4+1] * inv;
        o.z = acc[i*4+2] * inv;
        o.w = acc[i*4+3] * inv;
        *(float4*)(optr + i * 4) = o;
    }
}

// ---------------------------------------------------------------------------
extern "C" void kernel_launch(void* const* d_in, const int* in_sizes, int n_in,
                              void* d_out, int out_size)
{
    const float* x    = (const float*)d_in[0];   // [2,2048,1024]
    const float* Wqkv = (const float*)d_in[1];   // [1024,3072]
    const float* bqkv = (const float*)d_in[2];   // [3072]
    const float* Wout = (const float*)d_in[3];   // [1024,1024]
    const float* bout = (const float*)d_in[4];   // [1024]
    float* out = (float*)d_out;                  // [2,2048,1024]

    float *qkv, *ctx;
    cudaGetSymbolAddress((void**)&qkv, g_qkv);
    cudaGetSymbolAddress((void**)&ctx, g_ctx);

    // 1) qkv = x @ Wqkv + bqkv
    sgemm_bias_kernel<<<dim3(QKV_N / 64, ROWS / 64), 256>>>(
        ROWS, QKV_N, DMODEL, x, Wqkv, bqkv, qkv);

    // 2) causal attention -> ctx  [B,S,D] with heads packed
    attn_kernel<<<dim3(SEQ / 64, BATCH * NHEADS), 64>>>(qkv, ctx);

    // 3) out = ctx @ Wout + bout
    sgemm_bias_kernel<<<dim3(DMODEL / 64, ROWS / 64), 256>>>(
        ROWS, DMODEL, DMODEL, ctx, Wout, bout, out);
}

// round 4
// speedup vs baseline: 1.6738x; 1.6738x over previous
#include <cuda_runtime.h>
#include <cuda_bf16.h>
#include <cstdint>
#include <cstddef>

// Problem constants
#define BATCH 2
#define SEQ   2048
#define DMODEL 1024
#define NHEADS 16
#define HD    64
#define ROWS  (BATCH*SEQ)          // 4096
#define QKV_N (3*DMODEL)           // 3072

// Scratch (allocation-free rule: __device__ globals)
__device__ float g_qkv[(size_t)ROWS * QKV_N];   // [row, 3*D]
__device__ float g_ctx[(size_t)ROWS * DMODEL];  // [row, D]

// ---------------------------------------------------------------------------
// helpers: tf32 convert, f32x2 packed math (sm_100+)
// ---------------------------------------------------------------------------
__device__ __forceinline__ uint32_t f2tf(float x) {
    uint32_t r;
    asm("cvt.rna.tf32.f32 %0, %1;" : "=r"(r) : "f"(x));
    return r;
}

typedef unsigned long long ull;

__device__ __forceinline__ ull fma2(ull a, ull b, ull c) {
    ull d;
    asm("fma.rn.f32x2 %0, %1, %2, %3;" : "=l"(d) : "l"(a), "l"(b), "l"(c));
    return d;
}
__device__ __forceinline__ ull add2(ull a, ull b) {
    ull d;
    asm("add.rn.f32x2 %0, %1, %2;" : "=l"(d) : "l"(a), "l"(b));
    return d;
}
__device__ __forceinline__ ull mul2(ull a, ull b) {
    ull d;
    asm("mul.rn.f32x2 %0, %1, %2;" : "=l"(d) : "l"(a), "l"(b));
    return d;
}
__device__ __forceinline__ ull pack2(float x, float y) {
    ull d;
    asm("mov.b64 %0, {%1, %2};" : "=l"(d) : "f"(x), "f"(y));
    return d;
}
__device__ __forceinline__ void unpack2(ull d, float& x, float& y) {
    asm("mov.b64 {%0, %1}, %2;" : "=f"(x), "=f"(y) : "l"(d));
}

__device__ __forceinline__ void mma_tf32(float* c, const uint32_t* a, const uint32_t* b) {
    asm volatile(
        "mma.sync.aligned.m16n8k8.row.col.f32.tf32.tf32.f32 "
        "{%0,%1,%2,%3}, {%4,%5,%6,%7}, {%8,%9}, {%0,%1,%2,%3};"
        : "+f"(c[0]), "+f"(c[1]), "+f"(c[2]), "+f"(c[3])
        : "r"(a[0]), "r"(a[1]), "r"(a[2]), "r"(a[3]), "r"(b[0]), "r"(b[1]));
}

// ---------------------------------------------------------------------------
// tf32 tensor-core GEMM: C[M,N] = A[M,K] @ B[K,N] + bias[N]
// BM=BN=128, BK=16, 256 threads = 8 warps (4 in M x 2 in N), warp tile 32x64
// ---------------------------------------------------------------------------
#define GBM 128
#define GBN 128
#define GBK 16

__global__ __launch_bounds__(256) void gemm_tf32_kernel(
    int M, int N, int K,
    const float* __restrict__ A,
    const float* __restrict__ B,
    const float* __restrict__ bias,
    float* __restrict__ C)
{
    // As[m][k] pad->20 (conflict-free frag loads), Bs[k][n] pad->136
    __shared__ uint32_t As[GBM][20];
    __shared__ uint32_t Bs[GBK][GBN + 8];

    const int tid  = threadIdx.x;
    const int warp = tid >> 5;
    const int lane = tid & 31;
    const int grp  = lane >> 2;   // 0..7
    const int tig  = lane & 3;    // 0..3
    const int wm   = (warp >> 1) * 32;  // warp M offset
    const int wn   = (warp & 1) * 64;   // warp N offset
    const int bm   = blockIdx.y * GBM;
    const int bn   = blockIdx.x * GBN;

    const float* Abase = A + (size_t)bm * K;
    const float* Bbase = B + bn;

    float acc[2][8][4];
    #pragma unroll
    for (int mi = 0; mi < 2; mi++)
        #pragma unroll
        for (int ni = 0; ni < 8; ni++)
            #pragma unroll
            for (int r = 0; r < 4; r++) acc[mi][ni][r] = 0.f;

    float4 ra[2], rb[2];

    // gmem index precompute: f in {tid, tid+256}
    // A: arow = f>>2 (0..127), ak = (f&3)*4 ; B: bk = f>>5 (0..15), bn4 = f&31
    auto ldA = [&](int k0) {
        #pragma unroll
        for (int u = 0; u < 2; u++) {
            int f = tid + u * 256;
            int arow = f >> 2, ak = (f & 3) * 4;
            ra[u] = *(const float4*)(Abase + (size_t)arow * K + k0 + ak);
        }
    };
    auto ldB = [&](int k0) {
        #pragma unroll
        for (int u = 0; u < 2; u++) {
            int f = tid + u * 256;
            int bk = f >> 5, bn4 = f & 31;
            rb[u] = *(const float4*)(Bbase + (size_t)(k0 + bk) * N + bn4 * 4);
        }
    };

    ldA(0); ldB(0);

    for (int k0 = 0; k0 < K; k0 += GBK) {
        __syncthreads();   // previous compute done reading smem
        // store staged tiles (cvt to tf32 bits)
        #pragma unroll
        for (int u = 0; u < 2; u++) {
            int f = tid + u * 256;
            int arow = f >> 2, ak = (f & 3) * 4;
            uint4 t;
            t.x = f2tf(ra[u].x); t.y = f2tf(ra[u].y);
            t.z = f2tf(ra[u].z); t.w = f2tf(ra[u].w);
            *(uint4*)&As[arow][ak] = t;
        }
        #pragma unroll
        for (int u = 0; u < 2; u++) {
            int f = tid + u * 256;
            int bk = f >> 5, bn4 = f & 31;
            uint4 t;
            t.x = f2tf(rb[u].x); t.y = f2tf(rb[u].y);
            t.z = f2tf(rb[u].z); t.w = f2tf(rb[u].w);
            *(uint4*)&Bs[bk][bn4 * 4] = t;
        }
        __syncthreads();

        if (k0 + GBK < K) { ldA(k0 + GBK); ldB(k0 + GBK); }

        #pragma unroll
        for (int ks = 0; ks < 2; ks++) {
            const int kb = ks * 8;
            uint32_t a[2][4], b[8][2];
            #pragma unroll
            for (int mi = 0; mi < 2; mi++) {
                int r0 = wm + mi * 16 + grp;
                a[mi][0] = As[r0    ][kb + tig];
                a[mi][1] = As[r0 + 8][kb + tig];
                a[mi][2] = As[r0    ][kb + tig + 4];
                a[mi][3] = As[r0 + 8][kb + tig + 4];
            }
            #pragma unroll
            for (int ni = 0; ni < 8; ni++) {
                int c0 = wn + ni * 8 + grp;
                b[ni][0] = Bs[kb + tig    ][c0];
                b[ni][1] = Bs[kb + tig + 4][c0];
            }
            #pragma unroll
            for (int mi = 0; mi < 2; mi++)
                #pragma unroll
                for (int ni = 0; ni < 8; ni++)
                    mma_tf32(acc[mi][ni], a[mi], b[ni]);
        }
    }

    // epilogue: c0=(grp,2t) c1=(grp,2t+1) c2=(grp+8,2t) c3=(grp+8,2t+1)
    #pragma unroll
    for (int mi = 0; mi < 2; mi++) {
        #pragma unroll
        for (int ni = 0; ni < 8; ni++) {
            int row0 = bm + wm + mi * 16 + grp;
            int col  = bn + wn + ni * 8 + tig * 2;
            float2 bv = *(const float2*)(bias + col);
            float2 o0, o1;
            o0.x = acc[mi][ni][0] + bv.x;
            o0.y = acc[mi][ni][1] + bv.y;
            o1.x = acc[mi][ni][2] + bv.x;
            o1.y = acc[mi][ni][3] + bv.y;
            *(float2*)(C + (size_t)row0 * N + col)       = o0;
            *(float2*)(C + (size_t)(row0 + 8) * N + col) = o1;
        }
    }
}

// ---------------------------------------------------------------------------
// Causal flash attention, fp32 math via packed f32x2.
// One block = 64 q rows of one (b,h); thread t owns q row t of the tile.
// ---------------------------------------------------------------------------
__global__ __launch_bounds__(64) void attn_kernel(
    const float* __restrict__ qkv, float* __restrict__ ctx)
{
    int qi = blockIdx.x;              // q tile 0..31
    int bh = blockIdx.y;
    int b  = bh >> 4;
    int h  = bh & 15;
    int t  = threadIdx.x;

    __shared__ __align__(16) float Ks[64][HD];
    __shared__ __align__(16) float Vs[64][HD];
    __shared__ float Ss[64][65];

    const float scale = 0.125f;
    int qrow = qi * 64 + t;

    const float* qptr = qkv + (size_t)(b * SEQ + qrow) * QKV_N + h * HD;
    ull qp[32];
    #pragma unroll
    for (int i = 0; i < 16; i++) {
        float4 v = *(const float4*)(qptr + i * 4);
        qp[2 * i]     = pack2(v.x, v.y);
        qp[2 * i + 1] = pack2(v.z, v.w);
    }

    ull ap[32];
    #pragma unroll
    for (int i = 0; i < 32; i++) ap[i] = 0ull;
    float m = -3.0e38f, l = 0.f;

    for (int kt = 0; kt <= qi; ++kt) {
        __syncthreads();
        const float* kbase = qkv + (size_t)(b * SEQ + kt * 64) * QKV_N + DMODEL + h * HD;
        #pragma unroll
        for (int i = 0; i < 16; i++) {
            int idx = i * 64 + t;
            int row = idx >> 4;
            int c4  = (idx & 15) * 4;
            const float* kp = kbase + (size_t)row * QKV_N + c4;
            *(float4*)&Ks[row][c4] = *(const float4*)kp;
            *(float4*)&Vs[row][c4] = *(const float4*)(kp + DMODEL);
        }
        __syncthreads();

        bool diag = (kt == qi);
        float mt = m;

        // Phase 1: scores (4 independent f32x2 chains)
        for (int j = 0; j < 64; ++j) {
            ull s0 = 0ull, s1 = 0ull, s2 = 0ull, s3 = 0ull;
            const ull* kp = (const ull*)&Ks[j][0];
            #pragma unroll
            for (int i = 0; i < 8; i++) {
                s0 = fma2(qp[4 * i + 0], kp[4 * i + 0], s0);
                s1 = fma2(qp[4 * i + 1], kp[4 * i + 1], s1);
                s2 = fma2(qp[4 * i + 2], kp[4 * i + 2], s2);
                s3 = fma2(qp[4 * i + 3], kp[4 * i + 3], s3);
            }
            ull sp = add2(add2(s0, s1), add2(s2, s3));
            float lo, hi;
            unpack2(sp, lo, hi);
            float s = (lo + hi) * scale;
            if (diag && j > t) s = -3.0e38f;
            Ss[t][j] = s;
            mt = fmaxf(mt, s);
        }

        // rescale
        float corr = __expf(m - mt);
        m = mt;
        l *= corr;
        ull cc = pack2(corr, corr);
        #pragma unroll
        for (int i = 0; i < 32; i++) ap[i] = mul2(ap[i], cc);

        // Phase 2: probs @ V
        for (int j = 0; j < 64; ++j) {
            float p = __expf(Ss[t][j] - m);
            l += p;
            ull pp = pack2(p, p);
            const ull* vp = (const ull*)&Vs[j][0];
            #pragma unroll
            for (int i = 0; i < 32; i++)
                ap[i] = fma2(pp, vp[i], ap[i]);
        }
    }

    float inv = 1.f / l;
    float* optr = ctx + (size_t)(b * SEQ + qrow) * DMODEL + h * HD;
    #pragma unroll
    for (int i = 0; i < 16; i++) {
        float x0, y0, x1, y1;
        unpack2(ap[2 * i], x0, y0);
        unpack2(ap[2 * i + 1], x1, y1);
        float4 o;
        o.x = x0 * inv; o.y = y0 * inv; o.z = x1 * inv; o.w = y1 * inv;
        *(float4*)(optr + i * 4) = o;
    }
}

// ---------------------------------------------------------------------------
extern "C" void kernel_launch(void* const* d_in, const int* in_sizes, int n_in,
                              void* d_out, int out_size)
{
    const float* x    = (const float*)d_in[0];   // [2,2048,1024]
    const float* Wqkv = (const float*)d_in[1];   // [1024,3072]
    const float* bqkv = (const float*)d_in[2];   // [3072]
    const float* Wout = (const float*)d_in[3];   // [1024,1024]
    const float* bout = (const float*)d_in[4];   // [1024]
    float* out = (float*)d_out;                  // [2,2048,1024]

    float *qkv, *ctx;
    cudaGetSymbolAddress((void**)&qkv, g_qkv);
    cudaGetSymbolAddress((void**)&ctx, g_ctx);

    // 1) qkv = x @ Wqkv + bqkv   (tf32 tensor cores)
    gemm_tf32_kernel<<<dim3(QKV_N / GBN, ROWS / GBM), 256>>>(
        ROWS, QKV_N, DMODEL, x, Wqkv, bqkv, qkv);

    // 2) causal attention -> ctx
    attn_kernel<<<dim3(SEQ / 64, BATCH * NHEADS), 64>>>(qkv, ctx);

    // 3) out = ctx @ Wout + bout (tf32 tensor cores)
    gemm_tf32_kernel<<<dim3(DMODEL / GBN, ROWS / GBM), 256>>>(
        ROWS, DMODEL, DMODEL, ctx, Wout, bout, out);
}

// round 6
// speedup vs baseline: 2.9388x; 1.7558x over previous
#include <cuda_runtime.h>
#include <cuda_bf16.h>
#include <cstdint>
#include <cstddef>

// Problem constants
#define BATCH 2
#define SEQ   2048
#define DMODEL 1024
#define NHEADS 16
#define HD    64
#define ROWS  (BATCH*SEQ)          // 4096
#define QKV_N (3*DMODEL)           // 3072

// Scratch (allocation-free rule: __device__ globals)
__device__ float g_qkv[(size_t)ROWS * QKV_N];   // [row, 3*D]
__device__ float g_ctx[(size_t)ROWS * DMODEL];  // [row, D]

// ---------------------------------------------------------------------------
// helpers
// ---------------------------------------------------------------------------
__device__ __forceinline__ uint32_t f2tf(float x) {
    uint32_t r;
    asm("cvt.rna.tf32.f32 %0, %1;" : "=r"(r) : "f"(x));
    return r;
}

__device__ __forceinline__ void mma_tf32(float* c, const uint32_t* a, const uint32_t* b) {
    asm volatile(
        "mma.sync.aligned.m16n8k8.row.col.f32.tf32.tf32.f32 "
        "{%0,%1,%2,%3}, {%4,%5,%6,%7}, {%8,%9}, {%0,%1,%2,%3};"
        : "+f"(c[0]), "+f"(c[1]), "+f"(c[2]), "+f"(c[3])
        : "r"(a[0]), "r"(a[1]), "r"(a[2]), "r"(a[3]), "r"(b[0]), "r"(b[1]));
}

// ---------------------------------------------------------------------------
// tf32 tensor-core GEMM: C[M,N] = A[M,K] @ B[K,N] + bias[N]
// BM=BN=128, BK=16, 256 threads = 8 warps (4 in M x 2 in N), warp tile 32x64
// ---------------------------------------------------------------------------
#define GBM 128
#define GBN 128
#define GBK 16

__global__ __launch_bounds__(256) void gemm_tf32_kernel(
    int M, int N, int K,
    const float* __restrict__ A,
    const float* __restrict__ B,
    const float* __restrict__ bias,
    float* __restrict__ C)
{
    __shared__ uint32_t As[GBM][20];
    __shared__ uint32_t Bs[GBK][GBN + 8];

    const int tid  = threadIdx.x;
    const int warp = tid >> 5;
    const int lane = tid & 31;
    const int grp  = lane >> 2;
    const int tig  = lane & 3;
    const int wm   = (warp >> 1) * 32;
    const int wn   = (warp & 1) * 64;
    const int bm   = blockIdx.y * GBM;
    const int bn   = blockIdx.x * GBN;

    const float* Abase = A + (size_t)bm * K;
    const float* Bbase = B + bn;

    float acc[2][8][4];
    #pragma unroll
    for (int mi = 0; mi < 2; mi++)
        #pragma unroll
        for (int ni = 0; ni < 8; ni++)
            #pragma unroll
            for (int r = 0; r < 4; r++) acc[mi][ni][r] = 0.f;

    float4 ra[2], rb[2];

    auto ldA = [&](int k0) {
        #pragma unroll
        for (int u = 0; u < 2; u++) {
            int f = tid + u * 256;
            int arow = f >> 2, ak = (f & 3) * 4;
            ra[u] = *(const float4*)(Abase + (size_t)arow * K + k0 + ak);
        }
    };
    auto ldB = [&](int k0) {
        #pragma unroll
        for (int u = 0; u < 2; u++) {
            int f = tid + u * 256;
            int bk = f >> 5, bn4 = f & 31;
            rb[u] = *(const float4*)(Bbase + (size_t)(k0 + bk) * N + bn4 * 4);
        }
    };

    ldA(0); ldB(0);

    for (int k0 = 0; k0 < K; k0 += GBK) {
        __syncthreads();
        #pragma unroll
        for (int u = 0; u < 2; u++) {
            int f = tid + u * 256;
            int arow = f >> 2, ak = (f & 3) * 4;
            uint4 t;
            t.x = f2tf(ra[u].x); t.y = f2tf(ra[u].y);
            t.z = f2tf(ra[u].z); t.w = f2tf(ra[u].w);
            *(uint4*)&As[arow][ak] = t;
        }
        #pragma unroll
        for (int u = 0; u < 2; u++) {
            int f = tid + u * 256;
            int bk = f >> 5, bn4 = f & 31;
            uint4 t;
            t.x = f2tf(rb[u].x); t.y = f2tf(rb[u].y);
            t.z = f2tf(rb[u].z); t.w = f2tf(rb[u].w);
            *(uint4*)&Bs[bk][bn4 * 4] = t;
        }
        __syncthreads();

        if (k0 + GBK < K) { ldA(k0 + GBK); ldB(k0 + GBK); }

        #pragma unroll
        for (int ks = 0; ks < 2; ks++) {
            const int kb = ks * 8;
            uint32_t a[2][4], b[8][2];
            #pragma unroll
            for (int mi = 0; mi < 2; mi++) {
                int r0 = wm + mi * 16 + grp;
                a[mi][0] = As[r0    ][kb + tig];
                a[mi][1] = As[r0 + 8][kb + tig];
                a[mi][2] = As[r0    ][kb + tig + 4];
                a[mi][3] = As[r0 + 8][kb + tig + 4];
            }
            #pragma unroll
            for (int ni = 0; ni < 8; ni++) {
                int c0 = wn + ni * 8 + grp;
                b[ni][0] = Bs[kb + tig    ][c0];
                b[ni][1] = Bs[kb + tig + 4][c0];
            }
            #pragma unroll
            for (int mi = 0; mi < 2; mi++)
                #pragma unroll
                for (int ni = 0; ni < 8; ni++)
                    mma_tf32(acc[mi][ni], a[mi], b[ni]);
        }
    }

    #pragma unroll
    for (int mi = 0; mi < 2; mi++) {
        #pragma unroll
        for (int ni = 0; ni < 8; ni++) {
            int row0 = bm + wm + mi * 16 + grp;
            int col  = bn + wn + ni * 8 + tig * 2;
            float2 bv = *(const float2*)(bias + col);
            float2 o0, o1;
            o0.x = acc[mi][ni][0] + bv.x;
            o0.y = acc[mi][ni][1] + bv.y;
            o1.x = acc[mi][ni][2] + bv.x;
            o1.y = acc[mi][ni][3] + bv.y;
            *(float2*)(C + (size_t)row0 * N + col)       = o0;
            *(float2*)(C + (size_t)(row0 + 8) * N + col) = o1;
        }
    }
}

// ---------------------------------------------------------------------------
// Tensor-core causal flash attention.
// Block = 128 q rows of one (b,h); 8 warps, warp owns 16 q rows.
// QK^T: 3xTF32 (hi/lo split, ~fp32 accuracy). PV: 1xTF32.
// All smem tiles stride 72 words -> every fragment access is bank-conflict-free.
// ---------------------------------------------------------------------------
#define BQ 128
#define BK 64
#define PSTR 72
#define ATTN_SMEM ((3 * BK * PSTR + BQ * PSTR) * 4)   // 92160 bytes

__global__ __launch_bounds__(256, 1) void attn_tc_kernel(
    const float* __restrict__ qkv, float* __restrict__ ctx)
{
    extern __shared__ float sm[];
    float* Kh = sm;                     // [BK][PSTR] K hi (tf32 bits)
    float* Kl = Kh + BK * PSTR;         // [BK][PSTR] K lo
    float* Vt = Kl + BK * PSTR;         // [BK][PSTR] V (tf32 bits)
    float* Ps = Vt + BK * PSTR;         // [BQ][PSTR] Q staging / probs

    const int qt = blockIdx.x;          // q tile (0..15)
    const int bh = blockIdx.y;
    const int b = bh >> 4, h = bh & 15;
    const int tid = threadIdx.x;
    const int w = tid >> 5, lane = tid & 31;
    const int grp = lane >> 2, tig = lane & 3;

    // --- stage Q*scale into Ps (coalesced) ---
    const float* qbase = qkv + (size_t)(b * SEQ + qt * BQ) * QKV_N + h * HD;
    #pragma unroll
    for (int u = 0; u < 8; u++) {
        int f = tid + u * 256;
        int r = f >> 4, c = (f & 15) * 4;
        float4 v = *(const float4*)(qbase + (size_t)r * QKV_N + c);
        v.x *= 0.125f; v.y *= 0.125f; v.z *= 0.125f; v.w *= 0.125f;
        *(float4*)(Ps + r * PSTR + c) = v;
    }
    __syncthreads();

    const int r0 = w * 16 + grp, r1 = r0 + 8;

    // --- Q fragments (hi/lo split), register resident ---
    uint32_t qh[8][4], ql[8][4];
    #pragma unroll
    for (int ks = 0; ks < 8; ks++) {
        int c0 = ks * 8 + tig;
        float x0 = Ps[r0 * PSTR + c0];
        float x1 = Ps[r1 * PSTR + c0];
        float x2 = Ps[r0 * PSTR + c0 + 4];
        float x3 = Ps[r1 * PSTR + c0 + 4];
        qh[ks][0] = f2tf(x0); ql[ks][0] = f2tf(x0 - __uint_as_float(qh[ks][0]));
        qh[ks][1] = f2tf(x1); ql[ks][1] = f2tf(x1 - __uint_as_float(qh[ks][1]));
        qh[ks][2] = f2tf(x2); ql[ks][2] = f2tf(x2 - __uint_as_float(qh[ks][2]));
        qh[ks][3] = f2tf(x3); ql[ks][3] = f2tf(x3 - __uint_as_float(qh[ks][3]));
    }

    float oacc[8][4];
    #pragma unroll
    for (int nt = 0; nt < 8; nt++)
        #pragma unroll
        for (int r = 0; r < 4; r++) oacc[nt][r] = 0.f;
    float m0 = -1e30f, m1 = -1e30f, l0 = 0.f, l1 = 0.f;

    const float* kvbase = qkv + (size_t)(b * SEQ) * QKV_N + DMODEL + h * HD;
    const int nkt = 2 * qt + 2;

    for (int kt = 0; kt < nkt; kt++) {
        __syncthreads();   // previous tile's smem reads complete
        // --- load K (hi/lo) + V tiles, cvt to tf32 ---
        const float* kb = kvbase + (size_t)(kt * BK) * QKV_N;
        #pragma unroll
        for (int u = 0; u < 4; u++) {
            int f = tid + u * 256;
            int j = f >> 4, c = (f & 15) * 4;
            const float* p = kb + (size_t)j * QKV_N + c;
            float4 kk = *(const float4*)p;
            float4 vv = *(const float4*)(p + DMODEL);
            uint4 khv, klv, vtv;
            khv.x = f2tf(kk.x); klv.x = f2tf(kk.x - __uint_as_float(khv.x));
            khv.y = f2tf(kk.y); klv.y = f2tf(kk.y - __uint_as_float(khv.y));
            khv.z = f2tf(kk.z); klv.z = f2tf(kk.z - __uint_as_float(khv.z));
            khv.w = f2tf(kk.w); klv.w = f2tf(kk.w - __uint_as_float(khv.w));
            vtv.x = f2tf(vv.x); vtv.y = f2tf(vv.y);
            vtv.z = f2tf(vv.z); vtv.w = f2tf(vv.w);
            *(uint4*)(Kh + j * PSTR + c) = khv;
            *(uint4*)(Kl + j * PSTR + c) = klv;
            *(uint4*)(Vt + j * PSTR + c) = vtv;
        }
        __syncthreads();

        // warp fully masked for this tile?
        if (kt * BK > qt * BQ + w * 16 + 15) continue;

        // --- QK^T (3xTF32) ---
        float s[8][4];
        #pragma unroll
        for (int nt = 0; nt < 8; nt++)
            #pragma unroll
            for (int r = 0; r < 4; r++) s[nt][r] = 0.f;

        #pragma unroll
        for (int ks = 0; ks < 8; ks++) {
            #pragma unroll
            for (int nt = 0; nt < 8; nt++) {
                int bi = (nt * 8 + grp) * PSTR + ks * 8 + tig;
                uint32_t bh2[2], bl2[2];
                bh2[0] = __float_as_uint(Kh[bi]);
                bh2[1] = __float_as_uint(Kh[bi + 4]);
                bl2[0] = __float_as_uint(Kl[bi]);
                bl2[1] = __float_as_uint(Kl[bi + 4]);
                mma_tf32(s[nt], qh[ks], bh2);
                mma_tf32(s[nt], qh[ks], bl2);
                mma_tf32(s[nt], ql[ks], bh2);
            }
        }

        // --- causal mask (diagonal tiles only) ---
        const int q0 = qt * BQ + r0, q1 = qt * BQ + r1;
        if (kt * BK + BK - 1 > q0) {
            #pragma unroll
            for (int nt = 0; nt < 8; nt++) {
                int jg = kt * BK + nt * 8 + 2 * tig;
                if (jg     > q0) s[nt][0] = -1e30f;
                if (jg + 1 > q0) s[nt][1] = -1e30f;
                if (jg     > q1) s[nt][2] = -1e30f;
                if (jg + 1 > q1) s[nt][3] = -1e30f;
            }
        }

        // --- online softmax ---
        float tm0 = -1e30f, tm1 = -1e30f;
        #pragma unroll
        for (int nt = 0; nt < 8; nt++) {
            tm0 = fmaxf(tm0, fmaxf(s[nt][0], s[nt][1]));
            tm1 = fmaxf(tm1, fmaxf(s[nt][2], s[nt][3]));
        }
        tm0 = fmaxf(tm0, __shfl_xor_sync(0xffffffffu, tm0, 1));
        tm0 = fmaxf(tm0, __shfl_xor_sync(0xffffffffu, tm0, 2));
        tm1 = fmaxf(tm1, __shfl_xor_sync(0xffffffffu, tm1, 1));
        tm1 = fmaxf(tm1, __shfl_xor_sync(0xffffffffu, tm1, 2));
        float nm0 = fmaxf(m0, tm0), nm1 = fmaxf(m1, tm1);
        float cr0 = __expf(m0 - nm0), cr1 = __expf(m1 - nm1);
        m0 = nm0; m1 = nm1;
        l0 *= cr0; l1 *= cr1;
        #pragma unroll
        for (int nt = 0; nt < 8; nt++) {
            oacc[nt][0] *= cr0; oacc[nt][1] *= cr0;
            oacc[nt][2] *= cr1; oacc[nt][3] *= cr1;
        }

        float ls0 = 0.f, ls1 = 0.f;
        #pragma unroll
        for (int nt = 0; nt < 8; nt++) {
            float p0 = __expf(s[nt][0] - m0);
            float p1 = __expf(s[nt][1] - m0);
            float p2 = __expf(s[nt][2] - m1);
            float p3 = __expf(s[nt][3] - m1);
            ls0 += p0 + p1; ls1 += p2 + p3;
            int cc = nt * 8 + 2 * tig;
            float2 w0, w1;
            w0.x = __uint_as_float(f2tf(p0)); w0.y = __uint_as_float(f2tf(p1));
            w1.x = __uint_as_float(f2tf(p2)); w1.y = __uint_as_float(f2tf(p3));
            *(float2*)(Ps + r0 * PSTR + cc) = w0;
            *(float2*)(Ps + r1 * PSTR + cc) = w1;
        }
        ls0 += __shfl_xor_sync(0xffffffffu, ls0, 1);
        ls0 += __shfl_xor_sync(0xffffffffu, ls0, 2);
        ls1 += __shfl_xor_sync(0xffffffffu, ls1, 1);
        ls1 += __shfl_xor_sync(0xffffffffu, ls1, 2);
        l0 += ls0; l1 += ls1;

        __syncwarp();   // P stores visible to PV fragment loads (same warp rows)

        // --- PV (1xTF32) ---
        #pragma unroll
        for (int ks = 0; ks < 8; ks++) {
            uint32_t a[4];
            int c0i = ks * 8 + tig;
            a[0] = __float_as_uint(Ps[r0 * PSTR + c0i]);
            a[1] = __float_as_uint(Ps[r1 * PSTR + c0i]);
            a[2] = __float_as_uint(Ps[r0 * PSTR + c0i + 4]);
            a[3] = __float_as_uint(Ps[r1 * PSTR + c0i + 4]);
            #pragma unroll
            for (int nt = 0; nt < 8; nt++) {
                uint32_t bb[2];
                int vi = (ks * 8 + tig) * PSTR + nt * 8 + grp;
                bb[0] = __float_as_uint(Vt[vi]);
                bb[1] = __float_as_uint(Vt[vi + 4 * PSTR]);
                mma_tf32(oacc[nt], a, bb);
            }
        }
    }

    // --- epilogue ---
    float inv0 = 1.f / l0, inv1 = 1.f / l1;
    float* ob = ctx + (size_t)(b * SEQ + qt * BQ) * DMODEL + h * HD;
    #pragma unroll
    for (int nt = 0; nt < 8; nt++) {
        int cc = nt * 8 + 2 * tig;
        float2 o0, o1;
        o0.x = oacc[nt][0] * inv0; o0.y = oacc[nt][1] * inv0;
        o1.x = oacc[nt][2] * inv1; o1.y = oacc[nt][3] * inv1;
        *(float2*)(ob + (size_t)r0 * DMODEL + cc) = o0;
        *(float2*)(ob + (size_t)r1 * DMODEL + cc) = o1;
    }
}

// ---------------------------------------------------------------------------
extern "C" void kernel_launch(void* const* d_in, const int* in_sizes, int n_in,
                              void* d_out, int out_size)
{
    const float* x    = (const float*)d_in[0];   // [2,2048,1024]
    const float* Wqkv = (const float*)d_in[1];   // [1024,3072]
    const float* bqkv = (const float*)d_in[2];   // [3072]
    const float* Wout = (const float*)d_in[3];   // [1024,1024]
    const float* bout = (const float*)d_in[4];   // [1024]
    float* out = (float*)d_out;                  // [2,2048,1024]

    float *qkv, *ctx;
    cudaGetSymbolAddress((void**)&qkv, g_qkv);
    cudaGetSymbolAddress((void**)&ctx, g_ctx);

    cudaFuncSetAttribute(attn_tc_kernel,
                         cudaFuncAttributeMaxDynamicSharedMemorySize, ATTN_SMEM);

    // 1) qkv = x @ Wqkv + bqkv   (tf32 tensor cores)
    gemm_tf32_kernel<<<dim3(QKV_N / GBN, ROWS / GBM), 256>>>(
        ROWS, QKV_N, DMODEL, x, Wqkv, bqkv, qkv);

    // 2) causal attention -> ctx (tf32 tensor cores, 3xTF32 QK^T)
    attn_tc_kernel<<<dim3(SEQ / BQ, BATCH * NHEADS), 256, ATTN_SMEM>>>(qkv, ctx);

    // 3) out = ctx @ Wout + bout (tf32 tensor cores)
    gemm_tf32_kernel<<<dim3(DMODEL / GBN, ROWS / GBM), 256>>>(
        ROWS, DMODEL, DMODEL, ctx, Wout, bout, out);
}

// round 8
// speedup vs baseline: 3.2474x; 1.1050x over previous
#include <cuda_runtime.h>
#include <cuda_bf16.h>
#include <cstdint>
#include <cstddef>

// Problem constants
#define BATCH 2
#define SEQ   2048
#define DMODEL 1024
#define NHEADS 16
#define HD    64
#define ROWS  (BATCH*SEQ)          // 4096
#define QKV_N (3*DMODEL)           // 3072

// Scratch (allocation-free rule: __device__ globals)
__device__ float g_qkv[(size_t)ROWS * QKV_N];    // [row, 3*D] full fp32 (attn input)
__device__ float g_ctx[(size_t)ROWS * DMODEL];   // [row, D] tf32-rounded (out-proj A)
__device__ float g_xr[(size_t)ROWS * DMODEL];    // tf32-rounded x
__device__ float g_wqkvr[(size_t)DMODEL * QKV_N];// tf32-rounded Wqkv
__device__ float g_woutr[(size_t)DMODEL * DMODEL];// tf32-rounded Wout

// ---------------------------------------------------------------------------
// helpers
// ---------------------------------------------------------------------------
__device__ __forceinline__ uint32_t f2tf(float x) {
    uint32_t r;
    asm("cvt.rna.tf32.f32 %0, %1;" : "=r"(r) : "f"(x));
    return r;
}

__device__ __forceinline__ void mma_tf32(float* c, const uint32_t* a, const uint32_t* b) {
    asm volatile(
        "mma.sync.aligned.m16n8k8.row.col.f32.tf32.tf32.f32 "
        "{%0,%1,%2,%3}, {%4,%5,%6,%7}, {%8,%9}, {%0,%1,%2,%3};"
        : "+f"(c[0]), "+f"(c[1]), "+f"(c[2]), "+f"(c[3])
        : "r"(a[0]), "r"(a[1]), "r"(a[2]), "r"(a[3]), "r"(b[0]), "r"(b[1]));
}

__device__ __forceinline__ void cpa16(void* smem, const void* gmem) {
    uint32_t sa = (uint32_t)__cvta_generic_to_shared(smem);
    asm volatile("cp.async.cg.shared.global [%0], [%1], 16;" :: "r"(sa), "l"(gmem));
}
#define CP_COMMIT() asm volatile("cp.async.commit_group;")
#define CP_WAIT1()  asm volatile("cp.async.wait_group 1;")

// ---------------------------------------------------------------------------
// prepass: round fp32 -> tf32-rounded fp32 (so GEMM can mma raw bits)
// ---------------------------------------------------------------------------
__global__ void round_tf32_kernel(const float4* __restrict__ src,
                                  float4* __restrict__ dst, int n4)
{
    int i = blockIdx.x * blockDim.x + threadIdx.x;
    if (i < n4) {
        float4 v = src[i];
        v.x = __uint_as_float(f2tf(v.x));
        v.y = __uint_as_float(f2tf(v.y));
        v.z = __uint_as_float(f2tf(v.z));
        v.w = __uint_as_float(f2tf(v.w));
        dst[i] = v;
    }
}

// ---------------------------------------------------------------------------
// tf32 tensor-core GEMM, cp.async 2-stage pipeline.
// C[M,N] = A[M,K] @ B[K,N] + bias[N].  A,B pre-rounded to tf32 values.
// BM=BN=128, BK=32, 256 threads = 8 warps (4Mx2N), warp tile 32x64.
// ---------------------------------------------------------------------------
#define GBM 128
#define GBN 128
#define GBK 32
#define ASTR 36
#define BSTR 136
#define GEMM_SMEM ((2*GBM*ASTR + 2*GBK*BSTR) * 4)   // 71680 B

__global__ __launch_bounds__(256, 2) void gemm_tf32_async(
    int M, int N, int K,
    const float* __restrict__ A,
    const float* __restrict__ B,
    const float* __restrict__ bias,
    float* __restrict__ C)
{
    extern __shared__ float gsm[];
    float* AsB = gsm;                    // [2][GBM][ASTR]
    float* BsB = gsm + 2 * GBM * ASTR;   // [2][GBK][BSTR]

    const int tid  = threadIdx.x;
    const int warp = tid >> 5;
    const int lane = tid & 31;
    const int grp  = lane >> 2;
    const int tig  = lane & 3;
    const int wm   = (warp >> 1) * 32;
    const int wn   = (warp & 1) * 64;
    const int bm   = blockIdx.y * GBM;
    const int bn   = blockIdx.x * GBN;

    const float* Abase = A + (size_t)bm * K;
    const float* Bbase = B + bn;

    float acc[2][8][4];
    #pragma unroll
    for (int mi = 0; mi < 2; mi++)
        #pragma unroll
        for (int ni = 0; ni < 8; ni++)
            #pragma unroll
            for (int r = 0; r < 4; r++) acc[mi][ni][r] = 0.f;

    auto loadStage = [&](int s, int k0) {
        float* Ab = AsB + s * (GBM * ASTR);
        float* Bb = BsB + s * (GBK * BSTR);
        #pragma unroll
        for (int u = 0; u < 4; u++) {
            int f = tid + u * 256;
            int r = f >> 3, k4 = (f & 7) * 4;
            cpa16(Ab + r * ASTR + k4, Abase + (size_t)r * K + k0 + k4);
        }
        #pragma unroll
        for (int u = 0; u < 4; u++) {
            int f = tid + u * 256;
            int r = f >> 5, c4 = (f & 31) * 4;
            cpa16(Bb + r * BSTR + c4, Bbase + (size_t)(k0 + r) * N + c4);
        }
    };

    loadStage(0, 0); CP_COMMIT();
    loadStage(1, GBK); CP_COMMIT();
    CP_WAIT1();
    __syncthreads();

    int cur = 0;
    for (int k0 = 0; k0 < K; k0 += GBK) {
        const float* Ab = AsB + cur * (GBM * ASTR);
        const float* Bb = BsB + cur * (GBK * BSTR);

        #pragma unroll
        for (int ks = 0; ks < 4; ks++) {
            const int kb = ks * 8;
            uint32_t a[2][4], b[8][2];
            #pragma unroll
            for (int mi = 0; mi < 2; mi++) {
                int r0 = wm + mi * 16 + grp;
                a[mi][0] = __float_as_uint(Ab[(size_t)r0 * ASTR + kb + tig]);
                a[mi][1] = __float_as_uint(Ab[(size_t)(r0 + 8) * ASTR + kb + tig]);
                a[mi][2] = __float_as_uint(Ab[(size_t)r0 * ASTR + kb + tig + 4]);
                a[mi][3] = __float_as_uint(Ab[(size_t)(r0 + 8) * ASTR + kb + tig + 4]);
            }
            #pragma unroll
            for (int ni = 0; ni < 8; ni++) {
                int c0 = wn + ni * 8 + grp;
                b[ni][0] = __float_as_uint(Bb[(size_t)(kb + tig) * BSTR + c0]);
                b[ni][1] = __float_as_uint(Bb[(size_t)(kb + tig + 4) * BSTR + c0]);
            }
            #pragma unroll
            for (int mi = 0; mi < 2; mi++)
                #pragma unroll
                for (int ni = 0; ni < 8; ni++)
                    mma_tf32(acc[mi][ni], a[mi], b[ni]);
        }

        __syncthreads();                  // all warps done reading stage cur
        int knext = k0 + 2 * GBK;
        if (knext < K) loadStage(cur, knext);
        CP_COMMIT();
        CP_WAIT1();
        __syncthreads();
        cur ^= 1;
    }

    #pragma unroll
    for (int mi = 0; mi < 2; mi++) {
        #pragma unroll
        for (int ni = 0; ni < 8; ni++) {
            int row0 = bm + wm + mi * 16 + grp;
            int col  = bn + wn + ni * 8 + tig * 2;
            float2 bv = *(const float2*)(bias + col);
            float2 o0, o1;
            o0.x = acc[mi][ni][0] + bv.x;
            o0.y = acc[mi][ni][1] + bv.y;
            o1.x = acc[mi][ni][2] + bv.x;
            o1.y = acc[mi][ni][3] + bv.y;
            *(float2*)(C + (size_t)row0 * N + col)       = o0;
            *(float2*)(C + (size_t)(row0 + 8) * N + col) = o1;
        }
    }
}

// ---------------------------------------------------------------------------
// Tensor-core causal flash attention.
// Block = 128 q rows of one (b,h); 8 warps, warp owns 16 q rows.
// QK^T: 3xTF32 (hi/lo split). PV: 1xTF32.
// K hi/lo interleaved -> LDS.64, conflict-free (stride 68 pairs).
// Ps stride 68 (A-frag conflict-free), Vt stride 72 (B-frag conflict-free).
// ---------------------------------------------------------------------------
#define BQ 128
#define BK 64
#define KSTR 68
#define VSTR 72
#define PSTR 68
#define ATTN_SMEM ((BK*KSTR*2 + BK*VSTR + BQ*PSTR) * 4)   // 88064 B

__global__ __launch_bounds__(256, 1) void attn_tc_kernel(
    const float* __restrict__ qkv, float* __restrict__ ctx)
{
    extern __shared__ float sm[];
    float* Khl = sm;                     // [BK][KSTR][2] hi/lo interleaved
    float* Vt  = Khl + BK * KSTR * 2;    // [BK][VSTR]
    float* Ps  = Vt + BK * VSTR;         // [BQ][PSTR]

    const int qt = gridDim.x - 1 - blockIdx.x;   // heavy tiles first
    const int bh = blockIdx.y;
    const int b = bh >> 4, h = bh & 15;
    const int tid = threadIdx.x;
    const int w = tid >> 5, lane = tid & 31;
    const int grp = lane >> 2, tig = lane & 3;

    // --- stage Q*scale into Ps (coalesced) ---
    const float* qbase = qkv + (size_t)(b * SEQ + qt * BQ) * QKV_N + h * HD;
    #pragma unroll
    for (int u = 0; u < 8; u++) {
        int f = tid + u * 256;
        int r = f >> 4, c = (f & 15) * 4;
        float4 v = *(const float4*)(qbase + (size_t)r * QKV_N + c);
        v.x *= 0.125f; v.y *= 0.125f; v.z *= 0.125f; v.w *= 0.125f;
        *(float4*)(Ps + r * PSTR + c) = v;
    }
    __syncthreads();

    const int r0 = w * 16 + grp, r1 = r0 + 8;

    // --- Q fragments (hi/lo split), register resident ---
    uint32_t qh[8][4], ql[8][4];
    #pragma unroll
    for (int ks = 0; ks < 8; ks++) {
        int c0 = ks * 8 + tig;
        float x0 = Ps[r0 * PSTR + c0];
        float x1 = Ps[r1 * PSTR + c0];
        float x2 = Ps[r0 * PSTR + c0 + 4];
        float x3 = Ps[r1 * PSTR + c0 + 4];
        qh[ks][0] = f2tf(x0); ql[ks][0] = f2tf(x0 - __uint_as_float(qh[ks][0]));
        qh[ks][1] = f2tf(x1); ql[ks][1] = f2tf(x1 - __uint_as_float(qh[ks][1]));
        qh[ks][2] = f2tf(x2); ql[ks][2] = f2tf(x2 - __uint_as_float(qh[ks][2]));
        qh[ks][3] = f2tf(x3); ql[ks][3] = f2tf(x3 - __uint_as_float(qh[ks][3]));
    }

    float oacc[8][4];
    #pragma unroll
    for (int nt = 0; nt < 8; nt++)
        #pragma unroll
        for (int r = 0; r < 4; r++) oacc[nt][r] = 0.f;
    float m0 = -1e30f, m1 = -1e30f, l0 = 0.f, l1 = 0.f;

    const float* kvbase = qkv + (size_t)(b * SEQ) * QKV_N + DMODEL + h * HD;
    const int nkt = 2 * qt + 2;

    for (int kt = 0; kt < nkt; kt++) {
        __syncthreads();
        // --- load K (hi/lo interleaved) + V tiles ---
        const float* kb_ = kvbase + (size_t)(kt * BK) * QKV_N;
        #pragma unroll
        for (int u = 0; u < 4; u++) {
            int f = tid + u * 256;
            int j = f >> 4, c = (f & 15) * 4;
            const float* p = kb_ + (size_t)j * QKV_N + c;
            float4 kk = *(const float4*)p;
            float4 vv = *(const float4*)(p + DMODEL);
            uint32_t h0 = f2tf(kk.x), l0b = f2tf(kk.x - __uint_as_float(h0));
            uint32_t h1 = f2tf(kk.y), l1b = f2tf(kk.y - __uint_as_float(h1));
            uint32_t h2 = f2tf(kk.z), l2b = f2tf(kk.z - __uint_as_float(h2));
            uint32_t h3 = f2tf(kk.w), l3b = f2tf(kk.w - __uint_as_float(h3));
            uint4 w0 = {h0, l0b, h1, l1b};
            uint4 w1 = {h2, l2b, h3, l3b};
            int base = (j * KSTR + c) * 2;
            *(uint4*)&Khl[base]     = w0;
            *(uint4*)&Khl[base + 4] = w1;
            uint4 vtv;
            vtv.x = f2tf(vv.x); vtv.y = f2tf(vv.y);
            vtv.z = f2tf(vv.z); vtv.w = f2tf(vv.w);
            *(uint4*)(Vt + j * VSTR + c) = vtv;
        }
        __syncthreads();

        if (kt * BK > qt * BQ + w * 16 + 15) continue;   // warp fully masked

        // --- QK^T (3xTF32), K hi/lo via LDS.64 ---
        float s[8][4];
        #pragma unroll
        for (int nt = 0; nt < 8; nt++)
            #pragma unroll
            for (int r = 0; r < 4; r++) s[nt][r] = 0.f;

        #pragma unroll
        for (int ks = 0; ks < 8; ks++) {
            #pragma unroll
            for (int nt = 0; nt < 8; nt++) {
                int bi = ((nt * 8 + grp) * KSTR + ks * 8 + tig) * 2;
                float2 p0 = *(const float2*)&Khl[bi];
                float2 p1 = *(const float2*)&Khl[bi + 8];
                uint32_t bh2[2], bl2[2];
                bh2[0] = __float_as_uint(p0.x); bh2[1] = __float_as_uint(p1.x);
                bl2[0] = __float_as_uint(p0.y); bl2[1] = __float_as_uint(p1.y);
                mma_tf32(s[nt], qh[ks], bh2);
                mma_tf32(s[nt], qh[ks], bl2);
                mma_tf32(s[nt], ql[ks], bh2);
            }
        }

        // --- causal mask (diagonal tiles only) ---
        const int q0 = qt * BQ + r0, q1 = qt * BQ + r1;
        if (kt * BK + BK - 1 > q0) {
            #pragma unroll
            for (int nt = 0; nt < 8; nt++) {
                int jg = kt * BK + nt * 8 + 2 * tig;
                if (jg     > q0) s[nt][0] = -1e30f;
                if (jg + 1 > q0) s[nt][1] = -1e30f;
                if (jg     > q1) s[nt][2] = -1e30f;
                if (jg + 1 > q1) s[nt][3] = -1e30f;
            }
        }

        // --- online softmax ---
        float tm0 = -1e30f, tm1 = -1e30f;
        #pragma unroll
        for (int nt = 0; nt < 8; nt++) {
            tm0 = fmaxf(tm0, fmaxf(s[nt][0], s[nt][1]));
            tm1 = fmaxf(tm1, fmaxf(s[nt][2], s[nt][3]));
        }
        tm0 = fmaxf(tm0, __shfl_xor_sync(0xffffffffu, tm0, 1));
        tm0 = fmaxf(tm0, __shfl_xor_sync(0xffffffffu, tm0, 2));
        tm1 = fmaxf(tm1, __shfl_xor_sync(0xffffffffu, tm1, 1));
        tm1 = fmaxf(tm1, __shfl_xor_sync(0xffffffffu, tm1, 2));
        float nm0 = fmaxf(m0, tm0), nm1 = fmaxf(m1, tm1);
        float cr0 = __expf(m0 - nm0), cr1 = __expf(m1 - nm1);
        m0 = nm0; m1 = nm1;
        l0 *= cr0; l1 *= cr1;
        #pragma unroll
        for (int nt = 0; nt < 8; nt++) {
            oacc[nt][0] *= cr0; oacc[nt][1] *= cr0;
            oacc[nt][2] *= cr1; oacc[nt][3] *= cr1;
        }

        float ls0 = 0.f, ls1 = 0.f;
        #pragma unroll
        for (int nt = 0; nt < 8; nt++) {
            float p0 = __expf(s[nt][0] - m0);
            float p1 = __expf(s[nt][1] - m0);
            float p2 = __expf(s[nt][2] - m1);
            float p3 = __expf(s[nt][3] - m1);
            ls0 += p0 + p1; ls1 += p2 + p3;
            int cc = nt * 8 + 2 * tig;
            float2 w0, w1;
            w0.x = __uint_as_float(f2tf(p0)); w0.y = __uint_as_float(f2tf(p1));
            w1.x = __uint_as_float(f2tf(p2)); w1.y = __uint_as_float(f2tf(p3));
            *(float2*)(Ps + r0 * PSTR + cc) = w0;
            *(float2*)(Ps + r1 * PSTR + cc) = w1;
        }
        ls0 += __shfl_xor_sync(0xffffffffu, ls0, 1);
        ls0 += __shfl_xor_sync(0xffffffffu, ls0, 2);
        ls1 += __shfl_xor_sync(0xffffffffu, ls1, 1);
        ls1 += __shfl_xor_sync(0xffffffffu, ls1, 2);
        l0 += ls0; l1 += ls1;

        __syncwarp();   // P stores visible to PV fragment loads (same-warp rows)

        // --- PV (1xTF32) ---
        #pragma unroll
        for (int ks = 0; ks < 8; ks++) {
            uint32_t a[4];
            int c0i = ks * 8 + tig;
            a[0] = __float_as_uint(Ps[r0 * PSTR + c0i]);
            a[1] = __float_as_uint(Ps[r1 * PSTR + c0i]);
            a[2] = __float_as_uint(Ps[r0 * PSTR + c0i + 4]);
            a[3] = __float_as_uint(Ps[r1 * PSTR + c0i + 4]);
            #pragma unroll
            for (int nt = 0; nt < 8; nt++) {
                uint32_t bb[2];
                int vi = (ks * 8 + tig) * VSTR + nt * 8 + grp;
                bb[0] = __float_as_uint(Vt[vi]);
                bb[1] = __float_as_uint(Vt[vi + 4 * VSTR]);
                mma_tf32(oacc[nt], a, bb);
            }
        }
    }

    // --- epilogue: write tf32-rounded ctx (out-proj consumes raw bits) ---
    float inv0 = 1.f / l0, inv1 = 1.f / l1;
    float* ob = ctx + (size_t)(b * SEQ + qt * BQ) * DMODEL + h * HD;
    #pragma unroll
    for (int nt = 0; nt < 8; nt++) {
        int cc = nt * 8 + 2 * tig;
        float2 o0, o1;
        o0.x = __uint_as_float(f2tf(oacc[nt][0] * inv0));
        o0.y = __uint_as_float(f2tf(oacc[nt][1] * inv0));
        o1.x = __uint_as_float(f2tf(oacc[nt][2] * inv1));
        o1.y = __uint_as_float(f2tf(oacc[nt][3] * inv1));
        *(float2*)(ob + (size_t)r0 * DMODEL + cc) = o0;
        *(float2*)(ob + (size_t)r1 * DMODEL + cc) = o1;
    }
}

// ---------------------------------------------------------------------------
extern "C" void kernel_launch(void* const* d_in, const int* in_sizes, int n_in,
                              void* d_out, int out_size)
{
    const float* x    = (const float*)d_in[0];
    const float* Wqkv = (const float*)d_in[1];
    const float* bqkv = (const float*)d_in[2];
    const float* Wout = (const float*)d_in[3];
    const float* bout = (const float*)d_in[4];
    float* out = (float*)d_out;

    float *qkv, *ctx, *xr, *wqkvr, *woutr;
    cudaGetSymbolAddress((void**)&qkv, g_qkv);
    cudaGetSymbolAddress((void**)&ctx, g_ctx);
    cudaGetSymbolAddress((void**)&xr, g_xr);
    cudaGetSymbolAddress((void**)&wqkvr, g_wqkvr);
    cudaGetSymbolAddress((void**)&woutr, g_woutr);

    cudaFuncSetAttribute(gemm_tf32_async,
                         cudaFuncAttributeMaxDynamicSharedMemorySize, GEMM_SMEM);
    cudaFuncSetAttribute(attn_tc_kernel,
                         cudaFuncAttributeMaxDynamicSharedMemorySize, ATTN_SMEM);

    // 0) prepass: tf32-round GEMM inputs
    {
        int n4x = ROWS * DMODEL / 4;
        int n4w = DMODEL * QKV_N / 4;
        int n4o = DMODEL * DMODEL / 4;
        round_tf32_kernel<<<(n4x + 255) / 256, 256>>>((const float4*)x, (float4*)xr, n4x);
        round_tf32_kernel<<<(n4w + 255) / 256, 256>>>((const float4*)Wqkv, (float4*)wqkvr, n4w);
        round_tf32_kernel<<<(n4o + 255) / 256, 256>>>((const float4*)Wout, (float4*)woutr, n4o);
    }

    // 1) qkv = x @ Wqkv + bqkv
    gemm_tf32_async<<<dim3(QKV_N / GBN, ROWS / GBM), 256, GEMM_SMEM>>>(
        ROWS, QKV_N, DMODEL, xr, wqkvr, bqkv, qkv);

    // 2) causal attention -> ctx (writes tf32-rounded)
    attn_tc_kernel<<<dim3(SEQ / BQ, BATCH * NHEADS), 256, ATTN_SMEM>>>(qkv, ctx);

    // 3) out = ctx @ Wout + bout
    gemm_tf32_async<<<dim3(DMODEL / GBN, ROWS / GBM), 256, GEMM_SMEM>>>(
        ROWS, DMODEL, DMODEL, ctx, woutr, bout, out);
}

// round 9
// speedup vs baseline: 3.3895x; 1.0438x over previous
#include <cuda_runtime.h>
#include <cuda_bf16.h>
#include <cstdint>
#include <cstddef>

// Problem constants
#define BATCH 2
#define SEQ   2048
#define DMODEL 1024
#define NHEADS 16
#define HD    64
#define ROWS  (BATCH*SEQ)          // 4096
#define QKV_N (3*DMODEL)           // 3072
#define BH    (BATCH*NHEADS)       // 32

// Scratch (allocation-free rule: __device__ globals)
__device__ float g_qs [(size_t)BH * SEQ * HD];      // Q*scale, fp32, head-major
__device__ float g_khl[(size_t)BH * SEQ * HD * 2];  // K hi/lo interleaved (tf32 vals)
__device__ float g_v  [(size_t)BH * SEQ * HD];      // V tf32-rounded, head-major
__device__ float g_ctx[(size_t)ROWS * DMODEL];      // ctx, tf32-rounded, [row][D]
__device__ float g_xr [(size_t)ROWS * DMODEL];      // tf32-rounded x
__device__ float g_wqkvr[(size_t)DMODEL * QKV_N];   // tf32-rounded Wqkv
__device__ float g_woutr[(size_t)DMODEL * DMODEL];  // tf32-rounded Wout

// ---------------------------------------------------------------------------
// helpers
// ---------------------------------------------------------------------------
__device__ __forceinline__ uint32_t f2tf(float x) {
    uint32_t r;
    asm("cvt.rna.tf32.f32 %0, %1;" : "=r"(r) : "f"(x));
    return r;
}

__device__ __forceinline__ void mma_tf32(float* c, const uint32_t* a, const uint32_t* b) {
    asm volatile(
        "mma.sync.aligned.m16n8k8.row.col.f32.tf32.tf32.f32 "
        "{%0,%1,%2,%3}, {%4,%5,%6,%7}, {%8,%9}, {%0,%1,%2,%3};"
        : "+f"(c[0]), "+f"(c[1]), "+f"(c[2]), "+f"(c[3])
        : "r"(a[0]), "r"(a[1]), "r"(a[2]), "r"(a[3]), "r"(b[0]), "r"(b[1]));
}

__device__ __forceinline__ void cpa16(void* smem, const void* gmem) {
    uint32_t sa = (uint32_t)__cvta_generic_to_shared(smem);
    asm volatile("cp.async.cg.shared.global [%0], [%1], 16;" :: "r"(sa), "l"(gmem));
}
#define CP_COMMIT() asm volatile("cp.async.commit_group;")
#define CP_WAIT1()  asm volatile("cp.async.wait_group 1;")

// ---------------------------------------------------------------------------
// prepass: round fp32 -> tf32-rounded fp32
// ---------------------------------------------------------------------------
__global__ void round_tf32_kernel(const float4* __restrict__ src,
                                  float4* __restrict__ dst, int n4)
{
    int i = blockIdx.x * blockDim.x + threadIdx.x;
    if (i < n4) {
        float4 v = src[i];
        v.x = __uint_as_float(f2tf(v.x));
        v.y = __uint_as_float(f2tf(v.y));
        v.z = __uint_as_float(f2tf(v.z));
        v.w = __uint_as_float(f2tf(v.w));
        dst[i] = v;
    }
}

// ---------------------------------------------------------------------------
// tf32 tensor-core GEMM, cp.async 2-stage pipeline.
// mode 0: C = A@B + bias (normal).
// mode 1: QKV scatter epilogue -> g_qs (Q*scale), g_khl (hi/lo), g_v (rounded),
//         head-major [bh][s][d].
// ---------------------------------------------------------------------------
#define GBM 128
#define GBN 128
#define GBK 32
#define ASTR 36
#define BSTR 136
#define GEMM_SMEM ((2*GBM*ASTR + 2*GBK*BSTR) * 4)   // 71680 B

__global__ __launch_bounds__(256, 2) void gemm_tf32_async(
    int M, int N, int K,
    const float* __restrict__ A,
    const float* __restrict__ B,
    const float* __restrict__ bias,
    float* __restrict__ C,
    float* __restrict__ qs, float* __restrict__ khl, float* __restrict__ vv,
    int mode)
{
    extern __shared__ float gsm[];
    float* AsB = gsm;
    float* BsB = gsm + 2 * GBM * ASTR;

    const int tid  = threadIdx.x;
    const int warp = tid >> 5;
    const int lane = tid & 31;
    const int grp  = lane >> 2;
    const int tig  = lane & 3;
    const int wm   = (warp >> 1) * 32;
    const int wn   = (warp & 1) * 64;
    const int bm   = blockIdx.y * GBM;
    const int bn   = blockIdx.x * GBN;

    const float* Abase = A + (size_t)bm * K;
    const float* Bbase = B + bn;

    float acc[2][8][4];
    #pragma unroll
    for (int mi = 0; mi < 2; mi++)
        #pragma unroll
        for (int ni = 0; ni < 8; ni++)
            #pragma unroll
            for (int r = 0; r < 4; r++) acc[mi][ni][r] = 0.f;

    auto loadStage = [&](int s, int k0) {
        float* Ab = AsB + s * (GBM * ASTR);
        float* Bb = BsB + s * (GBK * BSTR);
        #pragma unroll
        for (int u = 0; u < 4; u++) {
            int f = tid + u * 256;
            int r = f >> 3, k4 = (f & 7) * 4;
            cpa16(Ab + r * ASTR + k4, Abase + (size_t)r * K + k0 + k4);
        }
        #pragma unroll
        for (int u = 0; u < 4; u++) {
            int f = tid + u * 256;
            int r = f >> 5, c4 = (f & 31) * 4;
            cpa16(Bb + r * BSTR + c4, Bbase + (size_t)(k0 + r) * N + c4);
        }
    };

    loadStage(0, 0); CP_COMMIT();
    loadStage(1, GBK); CP_COMMIT();
    CP_WAIT1();
    __syncthreads();

    int cur = 0;
    for (int k0 = 0; k0 < K; k0 += GBK) {
        const float* Ab = AsB + cur * (GBM * ASTR);
        const float* Bb = BsB + cur * (GBK * BSTR);

        #pragma unroll
        for (int ks = 0; ks < 4; ks++) {
            const int kb = ks * 8;
            uint32_t a[2][4], b[8][2];
            #pragma unroll
            for (int mi = 0; mi < 2; mi++) {
                int r0 = wm + mi * 16 + grp;
                a[mi][0] = __float_as_uint(Ab[(size_t)r0 * ASTR + kb + tig]);
                a[mi][1] = __float_as_uint(Ab[(size_t)(r0 + 8) * ASTR + kb + tig]);
                a[mi][2] = __float_as_uint(Ab[(size_t)r0 * ASTR + kb + tig + 4]);
                a[mi][3] = __float_as_uint(Ab[(size_t)(r0 + 8) * ASTR + kb + tig + 4]);
            }
            #pragma unroll
            for (int ni = 0; ni < 8; ni++) {
                int c0 = wn + ni * 8 + grp;
                b[ni][0] = __float_as_uint(Bb[(size_t)(kb + tig) * BSTR + c0]);
                b[ni][1] = __float_as_uint(Bb[(size_t)(kb + tig + 4) * BSTR + c0]);
            }
            #pragma unroll
            for (int mi = 0; mi < 2; mi++)
                #pragma unroll
                for (int ni = 0; ni < 8; ni++)
                    mma_tf32(acc[mi][ni], a[mi], b[ni]);
        }

        __syncthreads();
        int knext = k0 + 2 * GBK;
        if (knext < K) loadStage(cur, knext);
        CP_COMMIT();
        CP_WAIT1();
        __syncthreads();
        cur ^= 1;
    }

    if (mode == 0) {
        #pragma unroll
        for (int mi = 0; mi < 2; mi++) {
            #pragma unroll
            for (int ni = 0; ni < 8; ni++) {
                int row0 = bm + wm + mi * 16 + grp;
                int col  = bn + wn + ni * 8 + tig * 2;
                float2 bv = *(const float2*)(bias + col);
                float2 o0, o1;
                o0.x = acc[mi][ni][0] + bv.x;
                o0.y = acc[mi][ni][1] + bv.y;
                o1.x = acc[mi][ni][2] + bv.x;
                o1.y = acc[mi][ni][3] + bv.y;
                *(float2*)(C + (size_t)row0 * N + col)       = o0;
                *(float2*)(C + (size_t)(row0 + 8) * N + col) = o1;
            }
        }
    } else {
        // QKV scatter: head-major, per-section conversion
        auto scatter = [&](int row, int col, float va, float vb) {
            int b2 = row >> 11, s = row & 2047;
            int sec = col >> 10;
            int h = (col & 1023) >> 6, d = col & 63;
            size_t base = ((size_t)((b2 << 4) + h) * SEQ + s) * HD + d;
            if (sec == 0) {
                float2 o = { va * 0.125f, vb * 0.125f };
                *(float2*)(qs + base) = o;
            } else if (sec == 1) {
                uint32_t h0 = f2tf(va), l0 = f2tf(va - __uint_as_float(h0));
                uint32_t h1 = f2tf(vb), l1 = f2tf(vb - __uint_as_float(h1));
                uint4 o = { h0, l0, h1, l1 };
                *(uint4*)(khl + base * 2) = o;
            } else {
                float2 o = { __uint_as_float(f2tf(va)), __uint_as_float(f2tf(vb)) };
                *(float2*)(vv + base) = o;
            }
        };
        #pragma unroll
        for (int mi = 0; mi < 2; mi++) {
            #pragma unroll
            for (int ni = 0; ni < 8; ni++) {
                int row0 = bm + wm + mi * 16 + grp;
                int col  = bn + wn + ni * 8 + tig * 2;
                float2 bv = *(const float2*)(bias + col);
                scatter(row0,     col, acc[mi][ni][0] + bv.x, acc[mi][ni][1] + bv.y);
                scatter(row0 + 8, col, acc[mi][ni][2] + bv.x, acc[mi][ni][3] + bv.y);
            }
        }
    }
}

// ---------------------------------------------------------------------------
// Tensor-core causal flash attention, cp.async 2-stage K/V pipeline.
// Inputs pre-converted head-major: qs (fp32*scale), khl (hi/lo tf32), v (tf32).
// Block = 128 q rows of one (b,h); 8 warps, warp owns 16 q rows.
// QK^T: 3xTF32.  PV: 1xTF32.
// ---------------------------------------------------------------------------
#define BQ 128
#define BK 64
#define KROW 136    // floats per Khl smem row (64 hi/lo pairs + 4 pad pairs)
#define VSTR 72
#define PSTR 68
#define KTILE (BK*KROW)
#define VTILE (BK*VSTR)
#define ATTN_SMEM ((2*KTILE + 2*VTILE + BQ*PSTR) * 4)   // 141312 B

__global__ __launch_bounds__(256, 1) void attn_tc_kernel(
    const float* __restrict__ qs, const float* __restrict__ khl,
    const float* __restrict__ vsrc, float* __restrict__ ctx)
{
    extern __shared__ float sm[];
    float* KhlS = sm;                       // [2][BK][KROW]
    float* VtS  = KhlS + 2 * KTILE;         // [2][BK][VSTR]
    float* Ps   = VtS + 2 * VTILE;          // [BQ][PSTR]

    const int qt = gridDim.x - 1 - blockIdx.x;   // heavy tiles first
    const int bh = blockIdx.y;
    const int b = bh >> 4;
    const int tid = threadIdx.x;
    const int w = tid >> 5, lane = tid & 31;
    const int grp = lane >> 2, tig = lane & 3;

    const float* kbase = khl + (size_t)bh * SEQ * (HD * 2);
    const float* vbase = vsrc + (size_t)bh * SEQ * HD;

    auto load_tile = [&](int kt, int stage) {
        const float* ks = kbase + (size_t)(kt * BK) * (HD * 2);
        float* kd = KhlS + stage * KTILE;
        #pragma unroll
        for (int u = 0; u < 8; u++) {
            int f = tid + u * 256;
            int j = f >> 5, c = (f & 31) * 4;
            cpa16(kd + j * KROW + c, ks + (size_t)j * (HD * 2) + c);
        }
        const float* vs = vbase + (size_t)(kt * BK) * HD;
        float* vd = VtS + stage * VTILE;
        #pragma unroll
        for (int u = 0; u < 4; u++) {
            int f = tid + u * 256;
            int j = f >> 4, c = (f & 15) * 4;
            cpa16(vd + j * VSTR + c, vs + (size_t)j * HD + c);
        }
    };

    const int nkt = 2 * qt + 2;

    // prologue: start K/V pipeline, then stage Q (LDG overlaps cp.async)
    load_tile(0, 0); CP_COMMIT();
    load_tile(1, 1); CP_COMMIT();

    const float* qsrc = qs + ((size_t)bh * SEQ + qt * BQ) * HD;
    #pragma unroll
    for (int u = 0; u < 8; u++) {
        int f = tid + u * 256;
        int r = f >> 4, c = (f & 15) * 4;
        *(float4*)(Ps + r * PSTR + c) = *(const float4*)(qsrc + (size_t)r * HD + c);
    }
    __syncthreads();

    const int r0 = w * 16 + grp, r1 = r0 + 8;

    // Q fragments (hi/lo split), register resident
    uint32_t qh[8][4], ql[8][4];
    #pragma unroll
    for (int ks = 0; ks < 8; ks++) {
        int c0 = ks * 8 + tig;
        float x0 = Ps[r0 * PSTR + c0];
        float x1 = Ps[r1 * PSTR + c0];
        float x2 = Ps[r0 * PSTR + c0 + 4];
        float x3 = Ps[r1 * PSTR + c0 + 4];
        qh[ks][0] = f2tf(x0); ql[ks][0] = f2tf(x0 - __uint_as_float(qh[ks][0]));
        qh[ks][1] = f2tf(x1); ql[ks][1] = f2tf(x1 - __uint_as_float(qh[ks][1]));
        qh[ks][2] = f2tf(x2); ql[ks][2] = f2tf(x2 - __uint_as_float(qh[ks][2]));
        qh[ks][3] = f2tf(x3); ql[ks][3] = f2tf(x3 - __uint_as_float(qh[ks][3]));
    }

    float oacc[8][4];
    #pragma unroll
    for (int nt = 0; nt < 8; nt++)
        #pragma unroll
        for (int r = 0; r < 4; r++) oacc[nt][r] = 0.f;
    float m0 = -1e30f, m1 = -1e30f, l0 = 0.f, l1 = 0.f;

    int cur = 0;
    for (int kt = 0; kt < nkt; kt++) {
        CP_WAIT1();
        __syncthreads();   // stage cur ready for all warps

        const bool active = (kt * BK <= qt * BQ + w * 16 + 15);
        if (active) {
            const float* Khl = KhlS + cur * KTILE;
            const float* Vt  = VtS + cur * VTILE;

            // --- QK^T (3xTF32), K hi/lo via LDS.64 ---
            float s[8][4];
            #pragma unroll
            for (int nt = 0; nt < 8; nt++)
                #pragma unroll
                for (int r = 0; r < 4; r++) s[nt][r] = 0.f;

            #pragma unroll
            for (int ks = 0; ks < 8; ks++) {
                #pragma unroll
                for (int nt = 0; nt < 8; nt++) {
                    int bi = (nt * 8 + grp) * KROW + (ks * 8 + tig) * 2;
                    float2 p0 = *(const float2*)&Khl[bi];
                    float2 p1 = *(const float2*)&Khl[bi + 8];
                    uint32_t bh2[2], bl2[2];
                    bh2[0] = __float_as_uint(p0.x); bh2[1] = __float_as_uint(p1.x);
                    bl2[0] = __float_as_uint(p0.y); bl2[1] = __float_as_uint(p1.y);
                    mma_tf32(s[nt], qh[ks], bh2);
                    mma_tf32(s[nt], qh[ks], bl2);
                    mma_tf32(s[nt], ql[ks], bh2);
                }
            }

            // --- causal mask (diagonal tiles only) ---
            const int q0 = qt * BQ + r0, q1 = qt * BQ + r1;
            if (kt * BK + BK - 1 > q0) {
                #pragma unroll
                for (int nt = 0; nt < 8; nt++) {
                    int jg = kt * BK + nt * 8 + 2 * tig;
                    if (jg     > q0) s[nt][0] = -1e30f;
                    if (jg + 1 > q0) s[nt][1] = -1e30f;
                    if (jg     > q1) s[nt][2] = -1e30f;
                    if (jg + 1 > q1) s[nt][3] = -1e30f;
                }
            }

            // --- online softmax ---
            float tm0 = -1e30f, tm1 = -1e30f;
            #pragma unroll
            for (int nt = 0; nt < 8; nt++) {
                tm0 = fmaxf(tm0, fmaxf(s[nt][0], s[nt][1]));
                tm1 = fmaxf(tm1, fmaxf(s[nt][2], s[nt][3]));
            }
            tm0 = fmaxf(tm0, __shfl_xor_sync(0xffffffffu, tm0, 1));
            tm0 = fmaxf(tm0, __shfl_xor_sync(0xffffffffu, tm0, 2));
            tm1 = fmaxf(tm1, __shfl_xor_sync(0xffffffffu, tm1, 1));
            tm1 = fmaxf(tm1, __shfl_xor_sync(0xffffffffu, tm1, 2));
            float nm0 = fmaxf(m0, tm0), nm1 = fmaxf(m1, tm1);
            float cr0 = __expf(m0 - nm0), cr1 = __expf(m1 - nm1);
            m0 = nm0; m1 = nm1;
            l0 *= cr0; l1 *= cr1;
            #pragma unroll
            for (int nt = 0; nt < 8; nt++) {
                oacc[nt][0] *= cr0; oacc[nt][1] *= cr0;
                oacc[nt][2] *= cr1; oacc[nt][3] *= cr1;
            }

            float ls0 = 0.f, ls1 = 0.f;
            #pragma unroll
            for (int nt = 0; nt < 8; nt++) {
                float p0 = __expf(s[nt][0] - m0);
                float p1 = __expf(s[nt][1] - m0);
                float p2 = __expf(s[nt][2] - m1);
                float p3 = __expf(s[nt][3] - m1);
                ls0 += p0 + p1; ls1 += p2 + p3;
                int cc = nt * 8 + 2 * tig;
                float2 w0, w1;
                w0.x = __uint_as_float(f2tf(p0)); w0.y = __uint_as_float(f2tf(p1));
                w1.x = __uint_as_float(f2tf(p2)); w1.y = __uint_as_float(f2tf(p3));
                *(float2*)(Ps + r0 * PSTR + cc) = w0;
                *(float2*)(Ps + r1 * PSTR + cc) = w1;
            }
            ls0 += __shfl_xor_sync(0xffffffffu, ls0, 1);
            ls0 += __shfl_xor_sync(0xffffffffu, ls0, 2);
            ls1 += __shfl_xor_sync(0xffffffffu, ls1, 1);
            ls1 += __shfl_xor_sync(0xffffffffu, ls1, 2);
            l0 += ls0; l1 += ls1;

            __syncwarp();   // P stores visible to same-warp fragment loads

            // --- PV (1xTF32) ---
            #pragma unroll
            for (int ks = 0; ks < 8; ks++) {
                uint32_t a[4];
                int c0i = ks * 8 + tig;
                a[0] = __float_as_uint(Ps[r0 * PSTR + c0i]);
                a[1] = __float_as_uint(Ps[r1 * PSTR + c0i]);
                a[2] = __float_as_uint(Ps[r0 * PSTR + c0i + 4]);
                a[3] = __float_as_uint(Ps[r1 * PSTR + c0i + 4]);
                #pragma unroll
                for (int nt = 0; nt < 8; nt++) {
                    uint32_t bb[2];
                    int vi = (ks * 8 + tig) * VSTR + nt * 8 + grp;
                    bb[0] = __float_as_uint(Vt[vi]);
                    bb[1] = __float_as_uint(Vt[vi + 4 * VSTR]);
                    mma_tf32(oacc[nt], a, bb);
                }
            }
        }

        __syncthreads();   // all warps done reading stage cur
        if (kt + 2 < nkt) load_tile(kt + 2, cur);
        CP_COMMIT();
        cur ^= 1;
    }

    // --- epilogue: write tf32-rounded ctx (out-proj consumes it as A) ---
    float inv0 = 1.f / l0, inv1 = 1.f / l1;
    const int h = bh & 15;
    float* ob = ctx + (size_t)(b * SEQ + qt * BQ) * DMODEL + h * HD;
    #pragma unroll
    for (int nt = 0; nt < 8; nt++) {
        int cc = nt * 8 + 2 * tig;
        float2 o0, o1;
        o0.x = __uint_as_float(f2tf(oacc[nt][0] * inv0));
        o0.y = __uint_as_float(f2tf(oacc[nt][1] * inv0));
        o1.x = __uint_as_float(f2tf(oacc[nt][2] * inv1));
        o1.y = __uint_as_float(f2tf(oacc[nt][3] * inv1));
        *(float2*)(ob + (size_t)r0 * DMODEL + cc) = o0;
        *(float2*)(ob + (size_t)r1 * DMODEL + cc) = o1;
    }
}

// ---------------------------------------------------------------------------
extern "C" void kernel_launch(void* const* d_in, const int* in_sizes, int n_in,
                              void* d_out, int out_size)
{
    const float* x    = (const float*)d_in[0];
    const float* Wqkv = (const float*)d_in[1];
    const float* bqkv = (const float*)d_in[2];
    const float* Wout = (const float*)d_in[3];
    const float* bout = (const float*)d_in[4];
    float* out = (float*)d_out;

    float *qs, *khl, *vv, *ctx, *xr, *wqkvr, *woutr;
    cudaGetSymbolAddress((void**)&qs, g_qs);
    cudaGetSymbolAddress((void**)&khl, g_khl);
    cudaGetSymbolAddress((void**)&vv, g_v);
    cudaGetSymbolAddress((void**)&ctx, g_ctx);
    cudaGetSymbolAddress((void**)&xr, g_xr);
    cudaGetSymbolAddress((void**)&wqkvr, g_wqkvr);
    cudaGetSymbolAddress((void**)&woutr, g_woutr);

    cudaFuncSetAttribute(gemm_tf32_async,
                         cudaFuncAttributeMaxDynamicSharedMemorySize, GEMM_SMEM);
    cudaFuncSetAttribute(attn_tc_kernel,
                         cudaFuncAttributeMaxDynamicSharedMemorySize, ATTN_SMEM);

    // 0) prepass: tf32-round GEMM inputs
    {
        int n4x = ROWS * DMODEL / 4;
        int n4w = DMODEL * QKV_N / 4;
        int n4o = DMODEL * DMODEL / 4;
        round_tf32_kernel<<<(n4x + 255) / 256, 256>>>((const float4*)x, (float4*)xr, n4x);
        round_tf32_kernel<<<(n4w + 255) / 256, 256>>>((const float4*)Wqkv, (float4*)wqkvr, n4w);
        round_tf32_kernel<<<(n4o + 255) / 256, 256>>>((const float4*)Wout, (float4*)woutr, n4o);
    }

    // 1) qkv projection with scatter epilogue -> qs/khl/v (head-major)
    gemm_tf32_async<<<dim3(QKV_N / GBN, ROWS / GBM), 256, GEMM_SMEM>>>(
        ROWS, QKV_N, DMODEL, xr, wqkvr, bqkv, nullptr, qs, khl, vv, 1);

    // 2) causal attention -> ctx (tf32-rounded)
    attn_tc_kernel<<<dim3(SEQ / BQ, BH), 256, ATTN_SMEM>>>(qs, khl, vv, ctx);

    // 3) out = ctx @ Wout + bout
    gemm_tf32_async<<<dim3(DMODEL / GBN, ROWS / GBM), 256, GEMM_SMEM>>>(
        ROWS, DMODEL, DMODEL, ctx, woutr, bout, out, nullptr, nullptr, nullptr, 0);
}

// round 10
// speedup vs baseline: 3.8648x; 1.1402x over previous
#include <cuda_runtime.h>
#include <cuda_bf16.h>
#include <cstdint>
#include <cstddef>

// Problem constants
#define BATCH 2
#define SEQ   2048
#define DMODEL 1024
#define NHEADS 16
#define HD    64
#define ROWS  (BATCH*SEQ)          // 4096
#define QKV_N (3*DMODEL)           // 3072
#define BH    (BATCH*NHEADS)       // 32

// Scratch (allocation-free rule: __device__ globals)
__device__ float    g_qs [(size_t)BH * SEQ * HD];     // Q*scale, fp32, head-major
__device__ uint32_t g_khl[(size_t)BH * SEQ * HD];     // K bf16 hi/lo: word[2p]=(h2p,h2p+1) word[2p+1]=(l2p,l2p+1)
__device__ float    g_v  [(size_t)BH * SEQ * HD];     // V tf32-rounded, head-major
__device__ float    g_ctx[(size_t)ROWS * DMODEL];     // ctx, tf32-rounded
__device__ float    g_xr [(size_t)ROWS * DMODEL];     // tf32-rounded x
__device__ float    g_wqkvr[(size_t)DMODEL * QKV_N];  // tf32-rounded Wqkv
__device__ float    g_woutr[(size_t)DMODEL * DMODEL]; // tf32-rounded Wout

// ---------------------------------------------------------------------------
// helpers
// ---------------------------------------------------------------------------
__device__ __forceinline__ uint32_t f2tf(float x) {
    uint32_t r;
    asm("cvt.rna.tf32.f32 %0, %1;" : "=r"(r) : "f"(x));
    return r;
}

__device__ __forceinline__ void mma_tf32(float* c, const uint32_t* a, const uint32_t* b) {
    asm volatile(
        "mma.sync.aligned.m16n8k8.row.col.f32.tf32.tf32.f32 "
        "{%0,%1,%2,%3}, {%4,%5,%6,%7}, {%8,%9}, {%0,%1,%2,%3};"
        : "+f"(c[0]), "+f"(c[1]), "+f"(c[2]), "+f"(c[3])
        : "r"(a[0]), "r"(a[1]), "r"(a[2]), "r"(a[3]), "r"(b[0]), "r"(b[1]));
}

__device__ __forceinline__ void mma_bf16(float* c, const uint32_t* a, const uint32_t* b) {
    asm volatile(
        "mma.sync.aligned.m16n8k16.row.col.f32.bf16.bf16.f32 "
        "{%0,%1,%2,%3}, {%4,%5,%6,%7}, {%8,%9}, {%0,%1,%2,%3};"
        : "+f"(c[0]), "+f"(c[1]), "+f"(c[2]), "+f"(c[3])
        : "r"(a[0]), "r"(a[1]), "r"(a[2]), "r"(a[3]), "r"(b[0]), "r"(b[1]));
}

// split (x,y) fp32 pair -> bf16x2 hi word + bf16x2 lo word (lo = residual)
__device__ __forceinline__ void split_bf16x2(float x, float y, uint32_t& h, uint32_t& l) {
    __nv_bfloat16 xh = __float2bfloat16(x);
    __nv_bfloat16 yh = __float2bfloat16(y);
    __nv_bfloat162 hh = __halves2bfloat162(xh, yh);
    __nv_bfloat162 ll = __halves2bfloat162(
        __float2bfloat16(x - __bfloat162float(xh)),
        __float2bfloat16(y - __bfloat162float(yh)));
    h = *(uint32_t*)&hh;
    l = *(uint32_t*)&ll;
}

__device__ __forceinline__ void cpa16(void* smem, const void* gmem) {
    uint32_t sa = (uint32_t)__cvta_generic_to_shared(smem);
    asm volatile("cp.async.cg.shared.global [%0], [%1], 16;" :: "r"(sa), "l"(gmem));
}
#define CP_COMMIT() asm volatile("cp.async.commit_group;")
#define CP_WAIT1()  asm volatile("cp.async.wait_group 1;")

// ---------------------------------------------------------------------------
// prepass: round fp32 -> tf32-rounded fp32
// ---------------------------------------------------------------------------
__global__ void round_tf32_kernel(const float4* __restrict__ src,
                                  float4* __restrict__ dst, int n4)
{
    int i = blockIdx.x * blockDim.x + threadIdx.x;
    if (i < n4) {
        float4 v = src[i];
        v.x = __uint_as_float(f2tf(v.x));
        v.y = __uint_as_float(f2tf(v.y));
        v.z = __uint_as_float(f2tf(v.z));
        v.w = __uint_as_float(f2tf(v.w));
        dst[i] = v;
    }
}

// ---------------------------------------------------------------------------
// tf32 tensor-core GEMM, cp.async 2-stage pipeline.
// mode 0: C = A@B + bias.  mode 1: QKV scatter epilogue (head-major).
// ---------------------------------------------------------------------------
#define GBM 128
#define GBN 128
#define GBK 32
#define ASTR 36
#define BSTR 136
#define GEMM_SMEM ((2*GBM*ASTR + 2*GBK*BSTR) * 4)   // 71680 B

__global__ __launch_bounds__(256, 2) void gemm_tf32_async(
    int M, int N, int K,
    const float* __restrict__ A,
    const float* __restrict__ B,
    const float* __restrict__ bias,
    float* __restrict__ C,
    float* __restrict__ qs, uint32_t* __restrict__ khl, float* __restrict__ vv,
    int mode)
{
    extern __shared__ float gsm[];
    float* AsB = gsm;
    float* BsB = gsm + 2 * GBM * ASTR;

    const int tid  = threadIdx.x;
    const int warp = tid >> 5;
    const int lane = tid & 31;
    const int grp  = lane >> 2;
    const int tig  = lane & 3;
    const int wm   = (warp >> 1) * 32;
    const int wn   = (warp & 1) * 64;
    const int bm   = blockIdx.y * GBM;
    const int bn   = blockIdx.x * GBN;

    const float* Abase = A + (size_t)bm * K;
    const float* Bbase = B + bn;

    float acc[2][8][4];
    #pragma unroll
    for (int mi = 0; mi < 2; mi++)
        #pragma unroll
        for (int ni = 0; ni < 8; ni++)
            #pragma unroll
            for (int r = 0; r < 4; r++) acc[mi][ni][r] = 0.f;

    auto loadStage = [&](int s, int k0) {
        float* Ab = AsB + s * (GBM * ASTR);
        float* Bb = BsB + s * (GBK * BSTR);
        #pragma unroll
        for (int u = 0; u < 4; u++) {
            int f = tid + u * 256;
            int r = f >> 3, k4 = (f & 7) * 4;
            cpa16(Ab + r * ASTR + k4, Abase + (size_t)r * K + k0 + k4);
        }
        #pragma unroll
        for (int u = 0; u < 4; u++) {
            int f = tid + u * 256;
            int r = f >> 5, c4 = (f & 31) * 4;
            cpa16(Bb + r * BSTR + c4, Bbase + (size_t)(k0 + r) * N + c4);
        }
    };

    loadStage(0, 0); CP_COMMIT();
    loadStage(1, GBK); CP_COMMIT();
    CP_WAIT1();
    __syncthreads();

    int cur = 0;
    for (int k0 = 0; k0 < K; k0 += GBK) {
        const float* Ab = AsB + cur * (GBM * ASTR);
        const float* Bb = BsB + cur * (GBK * BSTR);

        #pragma unroll
        for (int ks = 0; ks < 4; ks++) {
            const int kb = ks * 8;
            uint32_t a[2][4], b[8][2];
            #pragma unroll
            for (int mi = 0; mi < 2; mi++) {
                int r0 = wm + mi * 16 + grp;
                a[mi][0] = __float_as_uint(Ab[(size_t)r0 * ASTR + kb + tig]);
                a[mi][1] = __float_as_uint(Ab[(size_t)(r0 + 8) * ASTR + kb + tig]);
                a[mi][2] = __float_as_uint(Ab[(size_t)r0 * ASTR + kb + tig + 4]);
                a[mi][3] = __float_as_uint(Ab[(size_t)(r0 + 8) * ASTR + kb + tig + 4]);
            }
            #pragma unroll
            for (int ni = 0; ni < 8; ni++) {
                int c0 = wn + ni * 8 + grp;
                b[ni][0] = __float_as_uint(Bb[(size_t)(kb + tig) * BSTR + c0]);
                b[ni][1] = __float_as_uint(Bb[(size_t)(kb + tig + 4) * BSTR + c0]);
            }
            #pragma unroll
            for (int mi = 0; mi < 2; mi++)
                #pragma unroll
                for (int ni = 0; ni < 8; ni++)
                    mma_tf32(acc[mi][ni], a[mi], b[ni]);
        }

        __syncthreads();
        int knext = k0 + 2 * GBK;
        if (knext < K) loadStage(cur, knext);
        CP_COMMIT();
        CP_WAIT1();
        __syncthreads();
        cur ^= 1;
    }

    if (mode == 0) {
        #pragma unroll
        for (int mi = 0; mi < 2; mi++) {
            #pragma unroll
            for (int ni = 0; ni < 8; ni++) {
                int row0 = bm + wm + mi * 16 + grp;
                int col  = bn + wn + ni * 8 + tig * 2;
                float2 bv = *(const float2*)(bias + col);
                float2 o0, o1;
                o0.x = acc[mi][ni][0] + bv.x;
                o0.y = acc[mi][ni][1] + bv.y;
                o1.x = acc[mi][ni][2] + bv.x;
                o1.y = acc[mi][ni][3] + bv.y;
                *(float2*)(C + (size_t)row0 * N + col)       = o0;
                *(float2*)(C + (size_t)(row0 + 8) * N + col) = o1;
            }
        }
    } else {
        // QKV scatter: head-major; Q scaled fp32, K bf16 hi/lo pairs, V tf32
        auto scatter = [&](int row, int col, float va, float vb) {
            int b2 = row >> 11, s = row & 2047;
            int sec = col >> 10;
            int h = (col & 1023) >> 6, d = col & 63;
            size_t base = ((size_t)((b2 << 4) + h) * SEQ + s) * HD + d;
            if (sec == 0) {
                float2 o = { va * 0.125f, vb * 0.125f };
                *(float2*)(qs + base) = o;
            } else if (sec == 1) {
                uint2 o;
                split_bf16x2(va, vb, o.x, o.y);
                *(uint2*)(khl + base) = o;   // word[2p]=hi pair, word[2p+1]=lo pair
            } else {
                float2 o = { __uint_as_float(f2tf(va)), __uint_as_float(f2tf(vb)) };
                *(float2*)(vv + base) = o;
            }
        };
        #pragma unroll
        for (int mi = 0; mi < 2; mi++) {
            #pragma unroll
            for (int ni = 0; ni < 8; ni++) {
                int row0 = bm + wm + mi * 16 + grp;
                int col  = bn + wn + ni * 8 + tig * 2;
                float2 bv = *(const float2*)(bias + col);
                scatter(row0,     col, acc[mi][ni][0] + bv.x, acc[mi][ni][1] + bv.y);
                scatter(row0 + 8, col, acc[mi][ni][2] + bv.x, acc[mi][ni][3] + bv.y);
            }
        }
    }
}

// ---------------------------------------------------------------------------
// Tensor-core causal flash attention, cp.async 2-stage K/V pipeline.
// QK^T: 3xBF16 m16n8k16 (hi/lo split).  PV: 1xTF32 m16n8k8.
// Block = 128 q rows of one (b,h); 8 warps; 2 CTAs/SM.
// ---------------------------------------------------------------------------
#define BQ 128
#define BK 64
#define KROW 72     // uint32 words per K smem row (64 data + 8 pad) - conflict-free
#define VSTR 72
#define PSTR 68
#define KTILE (BK*KROW)
#define VTILE (BK*VSTR)
#define ATTN_SMEM ((2*KTILE + 2*VTILE + BQ*PSTR) * 4)   // 108544 B

__global__ __launch_bounds__(256, 2) void attn_tc_kernel(
    const float* __restrict__ qs, const uint32_t* __restrict__ khl,
    const float* __restrict__ vsrc, float* __restrict__ ctx)
{
    extern __shared__ float sm[];
    uint32_t* KhlS = (uint32_t*)sm;         // [2][BK][KROW]
    float* VtS = sm + 2 * KTILE;            // [2][BK][VSTR]
    float* Ps  = VtS + 2 * VTILE;           // [BQ][PSTR]

    const int qt = gridDim.x - 1 - blockIdx.x;   // heavy tiles first
    const int bh = blockIdx.y;
    const int b = bh >> 4;
    const int tid = threadIdx.x;
    const int w = tid >> 5, lane = tid & 31;
    const int grp = lane >> 2, tig = lane & 3;

    const uint32_t* kbase = khl + (size_t)bh * SEQ * HD;
    const float* vbase = vsrc + (size_t)bh * SEQ * HD;

    auto load_tile = [&](int kt, int stage) {
        const uint32_t* ks = kbase + (size_t)(kt * BK) * HD;
        uint32_t* kd = KhlS + stage * KTILE;
        #pragma unroll
        for (int u = 0; u < 4; u++) {
            int f = tid + u * 256;
            int j = f >> 4, c = (f & 15) * 4;
            cpa16(kd + j * KROW + c, ks + (size_t)j * HD + c);
        }
        const float* vs = vbase + (size_t)(kt * BK) * HD;
        float* vd = VtS + stage * VTILE;
        #pragma unroll
        for (int u = 0; u < 4; u++) {
            int f = tid + u * 256;
            int j = f >> 4, c = (f & 15) * 4;
            cpa16(vd + j * VSTR + c, vs + (size_t)j * HD + c);
        }
    };

    const int nkt = 2 * qt + 2;

    load_tile(0, 0); CP_COMMIT();
    load_tile(1, 1); CP_COMMIT();

    const float* qsrc = qs + ((size_t)bh * SEQ + qt * BQ) * HD;
    #pragma unroll
    for (int u = 0; u < 8; u++) {
        int f = tid + u * 256;
        int r = f >> 4, c = (f & 15) * 4;
        *(float4*)(Ps + r * PSTR + c) = *(const float4*)(qsrc + (size_t)r * HD + c);
    }
    __syncthreads();

    const int r0 = w * 16 + grp, r1 = r0 + 8;

    // Q fragments: bf16 hi/lo split, m16n8k16 layout, register resident
    uint32_t qh[4][4], ql[4][4];
    #pragma unroll
    for (int ks = 0; ks < 4; ks++) {
        int kb = ks * 16 + 2 * tig;
        float2 x0 = *(const float2*)(Ps + r0 * PSTR + kb);
        float2 x1 = *(const float2*)(Ps + r1 * PSTR + kb);
        float2 x2 = *(const float2*)(Ps + r0 * PSTR + kb + 8);
        float2 x3 = *(const float2*)(Ps + r1 * PSTR + kb + 8);
        split_bf16x2(x0.x, x0.y, qh[ks][0], ql[ks][0]);
        split_bf16x2(x1.x, x1.y, qh[ks][1], ql[ks][1]);
        split_bf16x2(x2.x, x2.y, qh[ks][2], ql[ks][2]);
        split_bf16x2(x3.x, x3.y, qh[ks][3], ql[ks][3]);
    }

    float oacc[8][4];
    #pragma unroll
    for (int nt = 0; nt < 8; nt++)
        #pragma unroll
        for (int r = 0; r < 4; r++) oacc[nt][r] = 0.f;
    float m0 = -1e30f, m1 = -1e30f, l0 = 0.f, l1 = 0.f;

    int cur = 0;
    for (int kt = 0; kt < nkt; kt++) {
        CP_WAIT1();
        __syncthreads();

        const bool active = (kt * BK <= qt * BQ + w * 16 + 15);
        if (active) {
            const uint32_t* Khl = KhlS + cur * KTILE;
            const float* Vt = VtS + cur * VTILE;

            // --- QK^T (3xBF16, m16n8k16) ---
            float s[8][4];
            #pragma unroll
            for (int nt = 0; nt < 8; nt++)
                #pragma unroll
                for (int r = 0; r < 4; r++) s[nt][r] = 0.f;

            #pragma unroll
            for (int ks = 0; ks < 4; ks++) {
                #pragma unroll
                for (int nt = 0; nt < 8; nt++) {
                    int bi = (nt * 8 + grp) * KROW + (ks * 8 + tig) * 2;
                    uint2 w0 = *(const uint2*)&Khl[bi];       // (hi, lo) for k-pair tig
                    uint2 w1 = *(const uint2*)&Khl[bi + 8];   // (hi, lo) for k-pair tig+4
                    uint32_t bh2[2] = { w0.x, w1.x };
                    uint32_t bl2[2] = { w0.y, w1.y };
                    mma_bf16(s[nt], qh[ks], bh2);
                    mma_bf16(s[nt], qh[ks], bl2);
                    mma_bf16(s[nt], ql[ks], bh2);
                }
            }

            // --- causal mask (diagonal tiles only) ---
            const int q0 = qt * BQ + r0, q1 = qt * BQ + r1;
            if (kt * BK + BK - 1 > q0) {
                #pragma unroll
                for (int nt = 0; nt < 8; nt++) {
                    int jg = kt * BK + nt * 8 + 2 * tig;
                    if (jg     > q0) s[nt][0] = -1e30f;
                    if (jg + 1 > q0) s[nt][1] = -1e30f;
                    if (jg     > q1) s[nt][2] = -1e30f;
                    if (jg + 1 > q1) s[nt][3] = -1e30f;
                }
            }

            // --- online softmax ---
            float tm0 = -1e30f, tm1 = -1e30f;
            #pragma unroll
            for (int nt = 0; nt < 8; nt++) {
                tm0 = fmaxf(tm0, fmaxf(s[nt][0], s[nt][1]));
                tm1 = fmaxf(tm1, fmaxf(s[nt][2], s[nt][3]));
            }
            tm0 = fmaxf(tm0, __shfl_xor_sync(0xffffffffu, tm0, 1));
            tm0 = fmaxf(tm0, __shfl_xor_sync(0xffffffffu, tm0, 2));
            tm1 = fmaxf(tm1, __shfl_xor_sync(0xffffffffu, tm1, 1));
            tm1 = fmaxf(tm1, __shfl_xor_sync(0xffffffffu, tm1, 2));
            float nm0 = fmaxf(m0, tm0), nm1 = fmaxf(m1, tm1);
            float cr0 = __expf(m0 - nm0), cr1 = __expf(m1 - nm1);
            m0 = nm0; m1 = nm1;
            l0 *= cr0; l1 *= cr1;
            #pragma unroll
            for (int nt = 0; nt < 8; nt++) {
                oacc[nt][0] *= cr0; oacc[nt][1] *= cr0;
                oacc[nt][2] *= cr1; oacc[nt][3] *= cr1;
            }

            float ls0 = 0.f, ls1 = 0.f;
            #pragma unroll
            for (int nt = 0; nt < 8; nt++) {
                float p0 = __expf(s[nt][0] - m0);
                float p1 = __expf(s[nt][1] - m0);
                float p2 = __expf(s[nt][2] - m1);
                float p3 = __expf(s[nt][3] - m1);
                ls0 += p0 + p1; ls1 += p2 + p3;
                int cc = nt * 8 + 2 * tig;
                float2 w0, w1;
                w0.x = __uint_as_float(f2tf(p0)); w0.y = __uint_as_float(f2tf(p1));
                w1.x = __uint_as_float(f2tf(p2)); w1.y = __uint_as_float(f2tf(p3));
                *(float2*)(Ps + r0 * PSTR + cc) = w0;
                *(float2*)(Ps + r1 * PSTR + cc) = w1;
            }
            ls0 += __shfl_xor_sync(0xffffffffu, ls0, 1);
            ls0 += __shfl_xor_sync(0xffffffffu, ls0, 2);
            ls1 += __shfl_xor_sync(0xffffffffu, ls1, 1);
            ls1 += __shfl_xor_sync(0xffffffffu, ls1, 2);
            l0 += ls0; l1 += ls1;

            __syncwarp();   // P stores visible to same-warp fragment loads

            // --- PV (1xTF32, m16n8k8) ---
            #pragma unroll
            for (int ks = 0; ks < 8; ks++) {
                uint32_t a[4];
                int c0i = ks * 8 + tig;
                a[0] = __float_as_uint(Ps[r0 * PSTR + c0i]);
                a[1] = __float_as_uint(Ps[r1 * PSTR + c0i]);
                a[2] = __float_as_uint(Ps[r0 * PSTR + c0i + 4]);
                a[3] = __float_as_uint(Ps[r1 * PSTR + c0i + 4]);
                #pragma unroll
                for (int nt = 0; nt < 8; nt++) {
                    uint32_t bb[2];
                    int vi = (ks * 8 + tig) * VSTR + nt * 8 + grp;
                    bb[0] = __float_as_uint(Vt[vi]);
                    bb[1] = __float_as_uint(Vt[vi + 4 * VSTR]);
                    mma_tf32(oacc[nt], a, bb);
                }
            }
        }

        __syncthreads();
        if (kt + 2 < nkt) load_tile(kt + 2, cur);
        CP_COMMIT();
        cur ^= 1;
    }

    // --- epilogue: write tf32-rounded ctx (out-proj consumes it as A) ---
    float inv0 = 1.f / l0, inv1 = 1.f / l1;
    const int h = bh & 15;
    float* ob = ctx + (size_t)(b * SEQ + qt * BQ) * DMODEL + h * HD;
    #pragma unroll
    for (int nt = 0; nt < 8; nt++) {
        int cc = nt * 8 + 2 * tig;
        float2 o0, o1;
        o0.x = __uint_as_float(f2tf(oacc[nt][0] * inv0));
        o0.y = __uint_as_float(f2tf(oacc[nt][1] * inv0));
        o1.x = __uint_as_float(f2tf(oacc[nt][2] * inv1));
        o1.y = __uint_as_float(f2tf(oacc[nt][3] * inv1));
        *(float2*)(ob + (size_t)r0 * DMODEL + cc) = o0;
        *(float2*)(ob + (size_t)r1 * DMODEL + cc) = o1;
    }
}

// ---------------------------------------------------------------------------
extern "C" void kernel_launch(void* const* d_in, const int* in_sizes, int n_in,
                              void* d_out, int out_size)
{
    const float* x    = (const float*)d_in[0];
    const float* Wqkv = (const float*)d_in[1];
    const float* bqkv = (const float*)d_in[2];
    const float* Wout = (const float*)d_in[3];
    const float* bout = (const float*)d_in[4];
    float* out = (float*)d_out;

    float *qs, *vv, *ctx, *xr, *wqkvr, *woutr;
    uint32_t* khl;
    cudaGetSymbolAddress((void**)&qs, g_qs);
    cudaGetSymbolAddress((void**)&khl, g_khl);
    cudaGetSymbolAddress((void**)&vv, g_v);
    cudaGetSymbolAddress((void**)&ctx, g_ctx);
    cudaGetSymbolAddress((void**)&xr, g_xr);
    cudaGetSymbolAddress((void**)&wqkvr, g_wqkvr);
    cudaGetSymbolAddress((void**)&woutr, g_woutr);

    cudaFuncSetAttribute(gemm_tf32_async,
                         cudaFuncAttributeMaxDynamicSharedMemorySize, GEMM_SMEM);
    cudaFuncSetAttribute(attn_tc_kernel,
                         cudaFuncAttributeMaxDynamicSharedMemorySize, ATTN_SMEM);

    // 0) prepass: tf32-round GEMM inputs
    {
        int n4x = ROWS * DMODEL / 4;
        int n4w = DMODEL * QKV_N / 4;
        int n4o = DMODEL * DMODEL / 4;
        round_tf32_kernel<<<(n4x + 255) / 256, 256>>>((const float4*)x, (float4*)xr, n4x);
        round_tf32_kernel<<<(n4w + 255) / 256, 256>>>((const float4*)Wqkv, (float4*)wqkvr, n4w);
        round_tf32_kernel<<<(n4o + 255) / 256, 256>>>((const float4*)Wout, (float4*)woutr, n4o);
    }

    // 1) qkv projection with scatter epilogue -> qs / khl(bf16 hi-lo) / v
    gemm_tf32_async<<<dim3(QKV_N / GBN, ROWS / GBM), 256, GEMM_SMEM>>>(
        ROWS, QKV_N, DMODEL, xr, wqkvr, bqkv, nullptr, qs, khl, vv, 1);

    // 2) causal attention -> ctx (tf32-rounded)
    attn_tc_kernel<<<dim3(SEQ / BQ, BH), 256, ATTN_SMEM>>>(qs, khl, vv, ctx);

    // 3) out = ctx @ Wout + bout
    gemm_tf32_async<<<dim3(DMODEL / GBN, ROWS / GBM), 256, GEMM_SMEM>>>(
        ROWS, DMODEL, DMODEL, ctx, woutr, bout, out, nullptr, nullptr, nullptr, 0);
}